// round 11
// baseline (speedup 1.0000x reference)
#include <cuda_runtime.h>
#include <math_constants.h>

#define NB  32
#define C   64
#define HW  1024
#define CHW 65536
#define EPS 1e-5f
#define JT  128
#define IC  64
#define LSCALE 0.180336880f   // 0.125 * log2(e)

// ---------------- scratch ----------------------------------------------------
__device__ float g_qn[NB * CHW];
__device__ float g_q [NB * CHW];           // tf32-rounded, pre-scaled by LSCALE
__device__ float g_kt[NB * CHW];           // K transposed [n][i][c], tf32-rounded
__device__ float g_v [NB * CHW];           // tf32-rounded
__device__ float g_part[96][4][2];         // LN partial sums

// ---------------- helpers ----------------------------------------------------
__device__ __forceinline__ unsigned f2tf(float x) {
    unsigned u;
    asm("cvt.rna.tf32.f32 %0, %1;" : "=r"(u) : "f"(x));
    return u;
}
__device__ __forceinline__ float ex2(float x) {
    float y;
    asm("ex2.approx.f32 %0, %1;" : "=f"(y) : "f"(x));
    return y;
}
__device__ __forceinline__ void mma_tf32(float* d, const unsigned* a, const unsigned* b) {
    asm volatile(
        "mma.sync.aligned.m16n8k8.row.col.f32.tf32.tf32.f32 "
        "{%0,%1,%2,%3}, {%4,%5,%6,%7}, {%8,%9}, {%0,%1,%2,%3};\n"
        : "+f"(d[0]), "+f"(d[1]), "+f"(d[2]), "+f"(d[3])
        : "r"(a[0]), "r"(a[1]), "r"(a[2]), "r"(a[3]), "r"(b[0]), "r"(b[1]));
}
__device__ __forceinline__ void cp16(unsigned dst, const void* src) {
    asm volatile("cp.async.cg.shared.global [%0], [%1], 16;" :: "r"(dst), "l"(src));
}
#define CP_COMMIT() asm volatile("cp.async.commit_group;")
#define CP_WAIT0()  asm volatile("cp.async.wait_group 0;")

// ---------------- 1a. LN stats: grid (96, 4), 256 thr -----------------------
__global__ __launch_bounds__(256) void ln_stats_kernel(
    const float* __restrict__ q, const float* __restrict__ k, const float* __restrict__ v)
{
    int t     = blockIdx.x;
    int quart = blockIdx.y;
    int which = t % 3, n = t / 3;
    const float* x = (which == 0 ? q : which == 1 ? k : v) + (size_t)n * CHW + quart * 16384;

    int tid = threadIdx.x;
    float4 a4 = make_float4(0, 0, 0, 0), q4 = make_float4(0, 0, 0, 0);
    for (int i = tid * 4; i < 16384; i += 256 * 4) {
        float4 val = *(const float4*)(x + i);
        a4.x += val.x; a4.y += val.y; a4.z += val.z; a4.w += val.w;
        q4.x += val.x * val.x; q4.y += val.y * val.y;
        q4.z += val.z * val.z; q4.w += val.w * val.w;
    }
    float s  = a4.x + a4.y + a4.z + a4.w;
    float ss = q4.x + q4.y + q4.z + q4.w;

    __shared__ float sm[256], sm2[256];
    sm[tid] = s; sm2[tid] = ss;
    __syncthreads();
    for (int o = 128; o > 0; o >>= 1) {
        if (tid < o) { sm[tid] += sm[tid + o]; sm2[tid] += sm2[tid + o]; }
        __syncthreads();
    }
    if (tid == 0) { g_part[t][quart][0] = sm[0]; g_part[t][quart][1] = sm2[0]; }
}

// ---------------- 1b. LN apply (query only): grid (NB, 4) -------------------
__global__ __launch_bounds__(256) void ln_apply_q_kernel(
    const float* __restrict__ q,
    const float* __restrict__ w1, const float* __restrict__ b1)
{
    int n     = blockIdx.x;
    int quart = blockIdx.y;
    int t     = n * 3;
    size_t off = (size_t)n * CHW + quart * 16384;
    const float* x = q + off;
    float* dst = g_qn + off;
    const float* w = w1 + quart * 16384;
    const float* b = b1 + quart * 16384;

    float s = 0.f, ss = 0.f;
#pragma unroll
    for (int qq = 0; qq < 4; qq++) { s += g_part[t][qq][0]; ss += g_part[t][qq][1]; }
    float mean = s * (1.0f / CHW);
    float var  = ss * (1.0f / CHW) - mean * mean;
    float rstd = rsqrtf(var + EPS);

    int tid = threadIdx.x;
    for (int i = tid * 4; i < 16384; i += 256 * 4) {
        float4 val = *(const float4*)(x + i);
        float4 wv  = *(const float4*)(w + i);
        float4 bv  = *(const float4*)(b + i);
        float4 o4;
        o4.x = (val.x - mean) * rstd * wv.x + bv.x;
        o4.y = (val.y - mean) * rstd * wv.y + bv.y;
        o4.z = (val.z - mean) * rstd * wv.z + bv.z;
        o4.w = (val.w - mean) * rstd * wv.w + bv.w;
        *(float4*)(dst + i) = o4;
    }
}

// ---------------- 2. projection (LN fused for K/V); tf32 outputs ------------
__global__ __launch_bounds__(256) void proj_kernel(
    const float* __restrict__ key, const float* __restrict__ value,
    const float* __restrict__ wq, const float* __restrict__ bq,
    const float* __restrict__ wk, const float* __restrict__ bk,
    const float* __restrict__ wv, const float* __restrict__ bv,
    const float* __restrict__ ln2w, const float* __restrict__ ln2b,
    const float* __restrict__ ln3w, const float* __restrict__ ln3b)
{
    extern __shared__ unsigned psm[];
    unsigned* Ws = psm;              // [64 o][68]
    unsigned* Xs = psm + 64 * 68;    // [64 c][264]; T reuse needs 256*68

    int which = blockIdx.z;
    int n     = blockIdx.y;
    int p0    = blockIdx.x * 256;
    const float *W, *B;
    if (which == 0)      { W = wq; B = bq; }
    else if (which == 1) { W = wk; B = bk; }
    else                 { W = wv; B = bv; }
    float wscale = (which == 0) ? LSCALE : 1.0f;

    int tid = threadIdx.x;
    for (int idx = tid; idx < 64 * 16; idx += 256) {
        int o = idx >> 4, c4 = (idx & 15) << 2;
        float4 v = *(const float4*)(W + o * C + c4);
        *(uint4*)(Ws + o * 68 + c4) =
            make_uint4(f2tf(v.x * wscale), f2tf(v.y * wscale),
                       f2tf(v.z * wscale), f2tf(v.w * wscale));
    }

    if (which == 0) {
        const float* src = g_qn + (size_t)n * CHW;
        for (int idx = tid; idx < 64 * 64; idx += 256) {
            int c = idx >> 6, p4 = (idx & 63) << 2;
            float4 v = *(const float4*)(src + c * HW + p0 + p4);
            *(uint4*)(Xs + c * 264 + p4) =
                make_uint4(f2tf(v.x), f2tf(v.y), f2tf(v.z), f2tf(v.w));
        }
    } else {
        const float* raw = (which == 1 ? key : value) + (size_t)n * CHW;
        const float* lw  = (which == 1 ? ln2w : ln3w);
        const float* lb  = (which == 1 ? ln2b : ln3b);
        int t = n * 3 + which;
        float s = 0.f, ss = 0.f;
#pragma unroll
        for (int qq = 0; qq < 4; qq++) { s += g_part[t][qq][0]; ss += g_part[t][qq][1]; }
        float mean = s * (1.0f / CHW);
        float var  = ss * (1.0f / CHW) - mean * mean;
        float rstd = rsqrtf(var + EPS);
        for (int idx = tid; idx < 64 * 64; idx += 256) {
            int c = idx >> 6, p4 = (idx & 63) << 2;
            float4 xv = *(const float4*)(raw + c * HW + p0 + p4);
            float4 wv = *(const float4*)(lw  + c * HW + p0 + p4);
            float4 bv = *(const float4*)(lb  + c * HW + p0 + p4);
            float4 v;
            v.x = (xv.x - mean) * rstd * wv.x + bv.x;
            v.y = (xv.y - mean) * rstd * wv.y + bv.y;
            v.z = (xv.z - mean) * rstd * wv.z + bv.z;
            v.w = (xv.w - mean) * rstd * wv.w + bv.w;
            *(uint4*)(Xs + c * 264 + p4) =
                make_uint4(f2tf(v.x), f2tf(v.y), f2tf(v.z), f2tf(v.w));
        }
    }
    __syncthreads();

    int wid = tid >> 5, lane = tid & 31;
    int g = lane >> 2, tig = lane & 3;
    int wn = wid * 32;

    float acc[4][4][4] = {};
#pragma unroll
    for (int kk = 0; kk < 8; kk++) {
        int c0 = kk * 8;
        unsigned a[4][4], b[4][2];
#pragma unroll
        for (int mf = 0; mf < 4; mf++) {
            int r = mf * 16 + g;
            a[mf][0] = Ws[r * 68 + c0 + tig];
            a[mf][1] = Ws[(r + 8) * 68 + c0 + tig];
            a[mf][2] = Ws[r * 68 + c0 + tig + 4];
            a[mf][3] = Ws[(r + 8) * 68 + c0 + tig + 4];
        }
#pragma unroll
        for (int nf = 0; nf < 4; nf++) {
            int col = wn + nf * 8 + g;
            b[nf][0] = Xs[(c0 + tig) * 264 + col];
            b[nf][1] = Xs[(c0 + tig + 4) * 264 + col];
        }
#pragma unroll
        for (int mf = 0; mf < 4; mf++)
#pragma unroll
            for (int nf = 0; nf < 4; nf++)
                mma_tf32(acc[mf][nf], a[mf], b[nf]);
    }

    if (which != 1) {
        float* dst = (which == 0 ? g_q : g_v) + (size_t)n * CHW;
#pragma unroll
        for (int mf = 0; mf < 4; mf++) {
            int o = mf * 16 + g;
            float b0 = B[o] * wscale, b1 = B[o + 8] * wscale;
#pragma unroll
            for (int nf = 0; nf < 4; nf++) {
                int p = p0 + wn + nf * 8 + 2 * tig;
                *(uint2*)(dst + o * HW + p) =
                    make_uint2(f2tf(acc[mf][nf][0] + b0), f2tf(acc[mf][nf][1] + b0));
                *(uint2*)(dst + (o + 8) * HW + p) =
                    make_uint2(f2tf(acc[mf][nf][2] + b1), f2tf(acc[mf][nf][3] + b1));
            }
        }
    } else {
        __syncthreads();
        float* T = (float*)Xs;   // [256 p][68]
#pragma unroll
        for (int mf = 0; mf < 4; mf++) {
            int o = mf * 16 + g;
            float b0 = B[o], b1 = B[o + 8];
#pragma unroll
            for (int nf = 0; nf < 4; nf++) {
                int p = wn + nf * 8 + 2 * tig;
                T[p * 68 + o]           = acc[mf][nf][0] + b0;
                T[(p + 1) * 68 + o]     = acc[mf][nf][1] + b0;
                T[p * 68 + o + 8]       = acc[mf][nf][2] + b1;
                T[(p + 1) * 68 + o + 8] = acc[mf][nf][3] + b1;
            }
        }
        __syncthreads();
        float* dst = g_kt + (size_t)n * CHW;
        for (int idx = tid; idx < 256 * 16; idx += 256) {
            int p = idx >> 4, c4 = (idx & 15) << 2;
            uint4 v = make_uint4(f2tf(T[p * 68 + c4]),     f2tf(T[p * 68 + c4 + 1]),
                                 f2tf(T[p * 68 + c4 + 2]), f2tf(T[p * 68 + c4 + 3]));
            *(uint4*)(dst + (size_t)(p0 + p) * C + c4) = v;
        }
    }
}

// ---------------- 3. flash, 512 thr, kk-split warp pairs ---------------------
// grid = (8 jt, NB), block 512 (16 warps = 2 kk-halves x 2 i-groups x 4 j-groups)
// smem u32: QP[64*136]=8704 (Q staging / Ps / combine) | K0,K1,V0,V1[64*68]
//           | sums 256 | rcol 128   => 26496 u32 = 105984 B
#define OFF_QP  0
#define OFF_K0  8704
#define OFF_K1  (8704 + 4352)
#define OFF_V0  (8704 + 8704)
#define OFF_V1  (8704 + 8704 + 4352)
#define OFF_SUM (8704 + 8704 + 8704)
#define OFF_RC  (OFF_SUM + 256)
#define FLASH_U32 (OFF_RC + 128)

__global__ __launch_bounds__(512, 1) void flash_kernel(
    float* __restrict__ attn_out, float* __restrict__ xout)
{
    extern __shared__ unsigned fsm[];
    unsigned* Qs  = fsm + OFF_QP;
    unsigned* Ps  = fsm + OFF_QP;
    float*    PsF = (float*)Ps;
    float*    sums = (float*)(fsm + OFF_SUM);
    float*    rcol = (float*)(fsm + OFF_RC);

    int n  = blockIdx.y;
    int j0 = blockIdx.x * JT;
    int tid = threadIdx.x;
    const float* kt = g_kt + (size_t)n * CHW;
    const float* qp = g_q  + (size_t)n * CHW;
    const float* vp = g_v  + (size_t)n * CHW;

    unsigned sb = (unsigned)__cvta_generic_to_shared(fsm);

    int li[2], lc[2];
#pragma unroll
    for (int t = 0; t < 2; t++) {
        int idx = tid + t * 512;
        li[t] = idx >> 4; lc[t] = (idx & 15) << 2;
    }

    // preload K chunk 0 (Phase A)
#pragma unroll
    for (int t = 0; t < 2; t++)
        cp16(sb + ((OFF_K0 + li[t] * 68 + lc[t]) << 2), kt + (size_t)li[t] * C + lc[t]);
    CP_COMMIT();

    // Q staging [64 c][128 j]
    for (int idx = tid; idx < 64 * 32; idx += 512) {
        int c = idx >> 5, j4 = (idx & 31) << 2;
        *(uint4*)(Qs + c * 136 + j4) = *(const uint4*)(qp + c * HW + j0 + j4);
    }
    __syncthreads();

    int wid = tid >> 5, lane = tid & 31;
    int g = lane >> 2, tig = lane & 3;
    int kh  = wid & 1;                 // kk half
    int wm  = ((wid >> 1) & 1) * 32;   // i-group (mma1) / c-group (mma2)
    int wj  = (wid >> 2) * 32;         // j-group
    int kk0 = kh * 4;

    // Q fragments (32 regs: this warp's kk-half only)
    unsigned Qb[4][4][2];
#pragma unroll
    for (int kk = 0; kk < 4; kk++)
#pragma unroll
        for (int nf = 0; nf < 4; nf++) {
            int col = wj + nf * 8 + g;
            Qb[kk][nf][0] = Qs[((kk0 + kk) * 8 + tig) * 136 + col];
            Qb[kk][nf][1] = Qs[((kk0 + kk) * 8 + tig + 4) * 136 + col];
        }
    __syncthreads();   // Qs free

    // ---------------- Phase A: column sums of exp2(logits) -------------------
    float s_run[4][2];
#pragma unroll
    for (int nf = 0; nf < 4; nf++) { s_run[nf][0] = 0.f; s_run[nf][1] = 0.f; }

    for (int ch = 0; ch < 16; ch++) {
        CP_WAIT0();
        __syncthreads();
        if (ch < 15) {
            int i0n = (ch + 1) * IC;
            unsigned koff = ((ch + 1) & 1) ? OFF_K1 : OFF_K0;
#pragma unroll
            for (int t = 0; t < 2; t++)
                cp16(sb + ((koff + li[t] * 68 + lc[t]) << 2),
                     kt + (size_t)(i0n + li[t]) * C + lc[t]);
            CP_COMMIT();
        }
        unsigned* Ks = fsm + ((ch & 1) ? OFF_K1 : OFF_K0);

        float acc1[2][4][4] = {};
#pragma unroll
        for (int kk = 0; kk < 4; kk++) {
            int c0 = (kk0 + kk) * 8;
            unsigned a[2][4];
#pragma unroll
            for (int mf = 0; mf < 2; mf++) {
                int r = wm + mf * 16 + g;
                a[mf][0] = Ks[r * 68 + c0 + tig];
                a[mf][1] = Ks[(r + 8) * 68 + c0 + tig];
                a[mf][2] = Ks[r * 68 + c0 + tig + 4];
                a[mf][3] = Ks[(r + 8) * 68 + c0 + tig + 4];
            }
#pragma unroll
            for (int mf = 0; mf < 2; mf++)
#pragma unroll
                for (int nf = 0; nf < 4; nf++)
                    mma_tf32(acc1[mf][nf], a[mf], Qb[kk][nf]);
        }

        if (kh) {
#pragma unroll
            for (int mf = 0; mf < 2; mf++) {
                int il = wm + mf * 16 + g;
#pragma unroll
                for (int nf = 0; nf < 4; nf++) {
                    int col = wj + nf * 8 + 2 * tig;
                    *(float2*)(PsF + il * 136 + col)       = make_float2(acc1[mf][nf][0], acc1[mf][nf][1]);
                    *(float2*)(PsF + (il + 8) * 136 + col) = make_float2(acc1[mf][nf][2], acc1[mf][nf][3]);
                }
            }
        }
        __syncthreads();
        if (!kh) {
#pragma unroll
            for (int mf = 0; mf < 2; mf++) {
                int il = wm + mf * 16 + g;
#pragma unroll
                for (int nf = 0; nf < 4; nf++) {
                    int col = wj + nf * 8 + 2 * tig;
                    float2 p0 = *(const float2*)(PsF + il * 136 + col);
                    float2 p1 = *(const float2*)(PsF + (il + 8) * 136 + col);
                    s_run[nf][0] += ex2(acc1[mf][nf][0] + p0.x) + ex2(acc1[mf][nf][2] + p1.x);
                    s_run[nf][1] += ex2(acc1[mf][nf][1] + p0.y) + ex2(acc1[mf][nf][3] + p1.y);
                }
            }
        }
    }

    // reduce over g-lanes; combine 2 i-groups via smem (kh==0 warps only)
#pragma unroll
    for (int mask = 4; mask <= 16; mask <<= 1)
#pragma unroll
        for (int nf = 0; nf < 4; nf++)
#pragma unroll
            for (int par = 0; par < 2; par++)
                s_run[nf][par] += __shfl_xor_sync(0xFFFFFFFF, s_run[nf][par], mask);

    __syncthreads();   // all PsF reads done before sums region (separate) + reuse
    if (!kh && g == 0) {
        int wi = wm >> 5;
#pragma unroll
        for (int nf = 0; nf < 4; nf++)
#pragma unroll
            for (int par = 0; par < 2; par++)
                sums[wi * 128 + wj + nf * 8 + 2 * tig + par] = s_run[nf][par];
    }
    __syncthreads();
    if (tid < 128) rcol[tid] = 1.0f / (sums[tid] + sums[128 + tid]);

    // prefetch Phase B chunk 0 (K + V)
#pragma unroll
    for (int t = 0; t < 2; t++) {
        cp16(sb + ((OFF_K0 + li[t] * 68 + lc[t]) << 2), kt + (size_t)li[t] * C + lc[t]);
        cp16(sb + ((OFF_V0 + li[t] * 68 + lc[t]) << 2), vp + li[t] * HW + lc[t]);
    }
    CP_COMMIT();
    __syncthreads();

    float rj[4][2];
#pragma unroll
    for (int nf = 0; nf < 4; nf++)
#pragma unroll
        for (int par = 0; par < 2; par++)
            rj[nf][par] = rcol[wj + nf * 8 + 2 * tig + par];

    // ---------------- Phase B: normalized probs + V@P ------------------------
    float* ap = attn_out ? attn_out + (size_t)n * HW * HW + j0 : nullptr;
    float acc2[2][4][4] = {};

    for (int ch = 0; ch < 16; ch++) {
        CP_WAIT0();
        __syncthreads();
        if (ch < 15) {
            int i0n = (ch + 1) * IC;
            unsigned koff = ((ch + 1) & 1) ? OFF_K1 : OFF_K0;
            unsigned voff = ((ch + 1) & 1) ? OFF_V1 : OFF_V0;
#pragma unroll
            for (int t = 0; t < 2; t++) {
                cp16(sb + ((koff + li[t] * 68 + lc[t]) << 2),
                     kt + (size_t)(i0n + li[t]) * C + lc[t]);
                cp16(sb + ((voff + li[t] * 68 + lc[t]) << 2),
                     vp + li[t] * HW + i0n + lc[t]);
            }
            CP_COMMIT();
        }
        unsigned* Ks = fsm + ((ch & 1) ? OFF_K1 : OFF_K0);
        unsigned* Vs = fsm + ((ch & 1) ? OFF_V1 : OFF_V0);
        int i0 = ch * IC;

        float acc1[2][4][4] = {};
#pragma unroll
        for (int kk = 0; kk < 4; kk++) {
            int c0 = (kk0 + kk) * 8;
            unsigned a[2][4];
#pragma unroll
            for (int mf = 0; mf < 2; mf++) {
                int r = wm + mf * 16 + g;
                a[mf][0] = Ks[r * 68 + c0 + tig];
                a[mf][1] = Ks[(r + 8) * 68 + c0 + tig];
                a[mf][2] = Ks[r * 68 + c0 + tig + 4];
                a[mf][3] = Ks[(r + 8) * 68 + c0 + tig + 4];
            }
#pragma unroll
            for (int mf = 0; mf < 2; mf++)
#pragma unroll
                for (int nf = 0; nf < 4; nf++)
                    mma_tf32(acc1[mf][nf], a[mf], Qb[kk][nf]);
        }

        if (kh) {
#pragma unroll
            for (int mf = 0; mf < 2; mf++) {
                int il = wm + mf * 16 + g;
#pragma unroll
                for (int nf = 0; nf < 4; nf++) {
                    int col = wj + nf * 8 + 2 * tig;
                    *(float2*)(PsF + il * 136 + col)       = make_float2(acc1[mf][nf][0], acc1[mf][nf][1]);
                    *(float2*)(PsF + (il + 8) * 136 + col) = make_float2(acc1[mf][nf][2], acc1[mf][nf][3]);
                }
            }
        }
        __syncthreads();
        if (!kh) {
#pragma unroll
            for (int mf = 0; mf < 2; mf++) {
                int il = wm + mf * 16 + g;
#pragma unroll
                for (int nf = 0; nf < 4; nf++) {
                    int col = wj + nf * 8 + 2 * tig;
                    float2 q0 = *(const float2*)(PsF + il * 136 + col);
                    float2 q1 = *(const float2*)(PsF + (il + 8) * 136 + col);
                    float pa = ex2(acc1[mf][nf][0] + q0.x) * rj[nf][0];
                    float pb = ex2(acc1[mf][nf][1] + q0.y) * rj[nf][1];
                    float pc = ex2(acc1[mf][nf][2] + q1.x) * rj[nf][0];
                    float pd = ex2(acc1[mf][nf][3] + q1.y) * rj[nf][1];
                    if (ap) {
                        *(float2*)(ap + (size_t)(i0 + il) * HW + col)     = make_float2(pa, pb);
                        *(float2*)(ap + (size_t)(i0 + il + 8) * HW + col) = make_float2(pc, pd);
                    }
                    *(uint2*)(Ps + il * 136 + col)       = make_uint2(f2tf(pa), f2tf(pb));
                    *(uint2*)(Ps + (il + 8) * 136 + col) = make_uint2(f2tf(pc), f2tf(pd));
                }
            }
        }
        __syncthreads();   // Ps holds tf32 probs

        if (xout) {
#pragma unroll
            for (int kk = 0; kk < 4; kk++) {
                int k0 = (kk0 + kk) * 8;
                unsigned a[2][4], b[4][2];
#pragma unroll
                for (int mf = 0; mf < 2; mf++) {
                    int r = wm + mf * 16 + g;   // c row
                    a[mf][0] = Vs[r * 68 + k0 + tig];
                    a[mf][1] = Vs[(r + 8) * 68 + k0 + tig];
                    a[mf][2] = Vs[r * 68 + k0 + tig + 4];
                    a[mf][3] = Vs[(r + 8) * 68 + k0 + tig + 4];
                }
#pragma unroll
                for (int nf = 0; nf < 4; nf++) {
                    int col = wj + nf * 8 + g;
                    b[nf][0] = Ps[(k0 + tig) * 136 + col];
                    b[nf][1] = Ps[(k0 + tig + 4) * 136 + col];
                }
#pragma unroll
                for (int mf = 0; mf < 2; mf++)
#pragma unroll
                    for (int nf = 0; nf < 4; nf++)
                        mma_tf32(acc2[mf][nf], a[mf], b[nf]);
            }
        }
    }

    if (!xout) return;

    // combine acc2 halves via PsF, add residual, store
    __syncthreads();
    if (kh) {
#pragma unroll
        for (int mf = 0; mf < 2; mf++) {
            int c = wm + mf * 16 + g;
#pragma unroll
            for (int nf = 0; nf < 4; nf++) {
                int col = wj + nf * 8 + 2 * tig;
                *(float2*)(PsF + c * 136 + col)       = make_float2(acc2[mf][nf][0], acc2[mf][nf][1]);
                *(float2*)(PsF + (c + 8) * 136 + col) = make_float2(acc2[mf][nf][2], acc2[mf][nf][3]);
            }
        }
    }
    __syncthreads();
    if (!kh) {
        const float* qn = g_qn + (size_t)n * CHW;
        float* xp = xout + (size_t)n * CHW;
#pragma unroll
        for (int mf = 0; mf < 2; mf++) {
            int c = wm + mf * 16 + g;
#pragma unroll
            for (int nf = 0; nf < 4; nf++) {
                int j = j0 + wj + nf * 8 + 2 * tig;
                int col = wj + nf * 8 + 2 * tig;
                float2 o0 = *(const float2*)(PsF + c * 136 + col);
                float2 o1 = *(const float2*)(PsF + (c + 8) * 136 + col);
                float2 q0 = *(const float2*)(qn + c * HW + j);
                float2 q1 = *(const float2*)(qn + (c + 8) * HW + j);
                *(float2*)(xp + c * HW + j) =
                    make_float2(acc2[mf][nf][0] + o0.x + q0.x, acc2[mf][nf][1] + o0.y + q0.y);
                *(float2*)(xp + (c + 8) * HW + j) =
                    make_float2(acc2[mf][nf][2] + o1.x + q1.x, acc2[mf][nf][3] + o1.y + q1.y);
            }
        }
    }
}

// ---------------------------------------------------------------------------
extern "C" void kernel_launch(void* const* d_in, const int* in_sizes, int n_in,
                              void* d_out, int out_size)
{
    const float* query = (const float*)d_in[0];
    const float* key   = (const float*)d_in[1];
    const float* value = (const float*)d_in[2];
    const float* ln1w  = (const float*)d_in[3];
    const float* ln1b  = (const float*)d_in[4];
    const float* ln2w  = (const float*)d_in[5];
    const float* ln2b  = (const float*)d_in[6];
    const float* ln3w  = (const float*)d_in[7];
    const float* ln3b  = (const float*)d_in[8];
    const float* wq    = (const float*)d_in[9];
    const float* bq    = (const float*)d_in[10];
    const float* wk    = (const float*)d_in[11];
    const float* bk    = (const float*)d_in[12];
    const float* wv    = (const float*)d_in[13];
    const float* bv    = (const float*)d_in[14];

    float* out = (float*)d_out;
    const size_t XSZ = (size_t)NB * CHW;
    const size_t ASZ = (size_t)NB * HW * HW;

    float* x_out    = nullptr;
    float* attn_out = nullptr;
    size_t osz = (size_t)out_size;
    if (osz >= XSZ + ASZ)      { x_out = out; attn_out = out + XSZ; }
    else if (osz == ASZ)       { attn_out = out; }
    else                       { x_out = out; }

    static int attr_set = 0;
    const int PROJ_SMEM  = (64 * 68 + 256 * 68) * 4;   // 87040
    const int FLASH_SMEM = FLASH_U32 * 4;              // 105984
    if (!attr_set) {
        cudaFuncSetAttribute(proj_kernel,
                             cudaFuncAttributeMaxDynamicSharedMemorySize, PROJ_SMEM);
        cudaFuncSetAttribute(flash_kernel,
                             cudaFuncAttributeMaxDynamicSharedMemorySize, FLASH_SMEM);
        attr_set = 1;
    }

    ln_stats_kernel<<<dim3(96, 4), 256>>>(query, key, value);
    ln_apply_q_kernel<<<dim3(NB, 4), 256>>>(query, ln1w, ln1b);
    proj_kernel<<<dim3(4, NB, 3), 256, PROJ_SMEM>>>(key, value, wq, bq, wk, bk, wv, bv,
                                                    ln2w, ln2b, ln3w, ln3b);
    flash_kernel<<<dim3(HW / JT, NB), 512, FLASH_SMEM>>>(attn_out, x_out);
}

// round 12
// speedup vs baseline: 1.2312x; 1.2312x over previous
#include <cuda_runtime.h>
#include <math_constants.h>

#define NB  32
#define C   64
#define HW  1024
#define CHW 65536
#define EPS 1e-5f
#define JT  128
#define IC  64
#define LSCALE 0.180336880f   // 0.125 * log2(e)

// ---------------- scratch ----------------------------------------------------
__device__ float g_qn[NB * CHW];
__device__ float g_q [NB * CHW];           // tf32-rounded, pre-scaled by LSCALE
__device__ float g_kt[NB * CHW];           // K transposed [n][i][c], tf32-rounded
__device__ float g_v [NB * CHW];           // tf32-rounded
__device__ float g_part[96][4][2];         // LN partial sums

// ---------------- helpers ----------------------------------------------------
__device__ __forceinline__ unsigned f2tf(float x) {
    unsigned u;
    asm("cvt.rna.tf32.f32 %0, %1;" : "=r"(u) : "f"(x));
    return u;
}
__device__ __forceinline__ float ex2(float x) {
    float y;
    asm("ex2.approx.f32 %0, %1;" : "=f"(y) : "f"(x));
    return y;
}
__device__ __forceinline__ void mma_tf32(float* d, const unsigned* a, const unsigned* b) {
    asm volatile(
        "mma.sync.aligned.m16n8k8.row.col.f32.tf32.tf32.f32 "
        "{%0,%1,%2,%3}, {%4,%5,%6,%7}, {%8,%9}, {%0,%1,%2,%3};\n"
        : "+f"(d[0]), "+f"(d[1]), "+f"(d[2]), "+f"(d[3])
        : "r"(a[0]), "r"(a[1]), "r"(a[2]), "r"(a[3]), "r"(b[0]), "r"(b[1]));
}
// tf32 a-fragment (m16k8) in ONE ldmatrix: four 8x(4xb32=16B) tiles.
__device__ __forceinline__ void ldsm4(unsigned* r, unsigned addr) {
    asm volatile("ldmatrix.sync.aligned.m8n8.x4.shared.b16 {%0,%1,%2,%3}, [%4];"
        : "=r"(r[0]), "=r"(r[1]), "=r"(r[2]), "=r"(r[3]) : "r"(addr));
}
__device__ __forceinline__ void cp16(unsigned dst, const void* src) {
    asm volatile("cp.async.cg.shared.global [%0], [%1], 16;" :: "r"(dst), "l"(src));
}
#define CP_COMMIT() asm volatile("cp.async.commit_group;")
#define CP_WAIT0()  asm volatile("cp.async.wait_group 0;")

// ---------------- 1a. LN stats: grid (96, 4), 256 thr -----------------------
__global__ __launch_bounds__(256) void ln_stats_kernel(
    const float* __restrict__ q, const float* __restrict__ k, const float* __restrict__ v)
{
    int t     = blockIdx.x;
    int quart = blockIdx.y;
    int which = t % 3, n = t / 3;
    const float* x = (which == 0 ? q : which == 1 ? k : v) + (size_t)n * CHW + quart * 16384;

    int tid = threadIdx.x;
    float4 a4 = make_float4(0, 0, 0, 0), q4 = make_float4(0, 0, 0, 0);
    for (int i = tid * 4; i < 16384; i += 256 * 4) {
        float4 val = *(const float4*)(x + i);
        a4.x += val.x; a4.y += val.y; a4.z += val.z; a4.w += val.w;
        q4.x += val.x * val.x; q4.y += val.y * val.y;
        q4.z += val.z * val.z; q4.w += val.w * val.w;
    }
    float s  = a4.x + a4.y + a4.z + a4.w;
    float ss = q4.x + q4.y + q4.z + q4.w;

    __shared__ float sm[256], sm2[256];
    sm[tid] = s; sm2[tid] = ss;
    __syncthreads();
    for (int o = 128; o > 0; o >>= 1) {
        if (tid < o) { sm[tid] += sm[tid + o]; sm2[tid] += sm2[tid + o]; }
        __syncthreads();
    }
    if (tid == 0) { g_part[t][quart][0] = sm[0]; g_part[t][quart][1] = sm2[0]; }
}

// ---------------- 1b. LN apply (query only): grid (NB, 4) -------------------
__global__ __launch_bounds__(256) void ln_apply_q_kernel(
    const float* __restrict__ q,
    const float* __restrict__ w1, const float* __restrict__ b1)
{
    int n     = blockIdx.x;
    int quart = blockIdx.y;
    int t     = n * 3;
    size_t off = (size_t)n * CHW + quart * 16384;
    const float* x = q + off;
    float* dst = g_qn + off;
    const float* w = w1 + quart * 16384;
    const float* b = b1 + quart * 16384;

    float s = 0.f, ss = 0.f;
#pragma unroll
    for (int qq = 0; qq < 4; qq++) { s += g_part[t][qq][0]; ss += g_part[t][qq][1]; }
    float mean = s * (1.0f / CHW);
    float var  = ss * (1.0f / CHW) - mean * mean;
    float rstd = rsqrtf(var + EPS);

    int tid = threadIdx.x;
    for (int i = tid * 4; i < 16384; i += 256 * 4) {
        float4 val = *(const float4*)(x + i);
        float4 wv  = *(const float4*)(w + i);
        float4 bv  = *(const float4*)(b + i);
        float4 o4;
        o4.x = (val.x - mean) * rstd * wv.x + bv.x;
        o4.y = (val.y - mean) * rstd * wv.y + bv.y;
        o4.z = (val.z - mean) * rstd * wv.z + bv.z;
        o4.w = (val.w - mean) * rstd * wv.w + bv.w;
        *(float4*)(dst + i) = o4;
    }
}

// ---------------- 2. projection (LN fused for K/V); tf32 outputs ------------
__global__ __launch_bounds__(256) void proj_kernel(
    const float* __restrict__ key, const float* __restrict__ value,
    const float* __restrict__ wq, const float* __restrict__ bq,
    const float* __restrict__ wk, const float* __restrict__ bk,
    const float* __restrict__ wv, const float* __restrict__ bv,
    const float* __restrict__ ln2w, const float* __restrict__ ln2b,
    const float* __restrict__ ln3w, const float* __restrict__ ln3b)
{
    extern __shared__ unsigned psm[];
    unsigned* Ws = psm;              // [64 o][68]
    unsigned* Xs = psm + 64 * 68;    // [64 c][264]; T reuse needs 256*68

    int which = blockIdx.z;
    int n     = blockIdx.y;
    int p0    = blockIdx.x * 256;
    const float *W, *B;
    if (which == 0)      { W = wq; B = bq; }
    else if (which == 1) { W = wk; B = bk; }
    else                 { W = wv; B = bv; }
    float wscale = (which == 0) ? LSCALE : 1.0f;

    int tid = threadIdx.x;
    for (int idx = tid; idx < 64 * 16; idx += 256) {
        int o = idx >> 4, c4 = (idx & 15) << 2;
        float4 v = *(const float4*)(W + o * C + c4);
        *(uint4*)(Ws + o * 68 + c4) =
            make_uint4(f2tf(v.x * wscale), f2tf(v.y * wscale),
                       f2tf(v.z * wscale), f2tf(v.w * wscale));
    }

    if (which == 0) {
        const float* src = g_qn + (size_t)n * CHW;
        for (int idx = tid; idx < 64 * 64; idx += 256) {
            int c = idx >> 6, p4 = (idx & 63) << 2;
            float4 v = *(const float4*)(src + c * HW + p0 + p4);
            *(uint4*)(Xs + c * 264 + p4) =
                make_uint4(f2tf(v.x), f2tf(v.y), f2tf(v.z), f2tf(v.w));
        }
    } else {
        const float* raw = (which == 1 ? key : value) + (size_t)n * CHW;
        const float* lw  = (which == 1 ? ln2w : ln3w);
        const float* lb  = (which == 1 ? ln2b : ln3b);
        int t = n * 3 + which;
        float s = 0.f, ss = 0.f;
#pragma unroll
        for (int qq = 0; qq < 4; qq++) { s += g_part[t][qq][0]; ss += g_part[t][qq][1]; }
        float mean = s * (1.0f / CHW);
        float var  = ss * (1.0f / CHW) - mean * mean;
        float rstd = rsqrtf(var + EPS);
        for (int idx = tid; idx < 64 * 64; idx += 256) {
            int c = idx >> 6, p4 = (idx & 63) << 2;
            float4 xv = *(const float4*)(raw + c * HW + p0 + p4);
            float4 wv = *(const float4*)(lw  + c * HW + p0 + p4);
            float4 bv = *(const float4*)(lb  + c * HW + p0 + p4);
            float4 v;
            v.x = (xv.x - mean) * rstd * wv.x + bv.x;
            v.y = (xv.y - mean) * rstd * wv.y + bv.y;
            v.z = (xv.z - mean) * rstd * wv.z + bv.z;
            v.w = (xv.w - mean) * rstd * wv.w + bv.w;
            *(uint4*)(Xs + c * 264 + p4) =
                make_uint4(f2tf(v.x), f2tf(v.y), f2tf(v.z), f2tf(v.w));
        }
    }
    __syncthreads();

    int wid = tid >> 5, lane = tid & 31;
    int g = lane >> 2, tig = lane & 3;
    int wn = wid * 32;

    float acc[4][4][4] = {};
#pragma unroll
    for (int kk = 0; kk < 8; kk++) {
        int c0 = kk * 8;
        unsigned a[4][4], b[4][2];
#pragma unroll
        for (int mf = 0; mf < 4; mf++) {
            int r = mf * 16 + g;
            a[mf][0] = Ws[r * 68 + c0 + tig];
            a[mf][1] = Ws[(r + 8) * 68 + c0 + tig];
            a[mf][2] = Ws[r * 68 + c0 + tig + 4];
            a[mf][3] = Ws[(r + 8) * 68 + c0 + tig + 4];
        }
#pragma unroll
        for (int nf = 0; nf < 4; nf++) {
            int col = wn + nf * 8 + g;
            b[nf][0] = Xs[(c0 + tig) * 264 + col];
            b[nf][1] = Xs[(c0 + tig + 4) * 264 + col];
        }
#pragma unroll
        for (int mf = 0; mf < 4; mf++)
#pragma unroll
            for (int nf = 0; nf < 4; nf++)
                mma_tf32(acc[mf][nf], a[mf], b[nf]);
    }

    if (which != 1) {
        float* dst = (which == 0 ? g_q : g_v) + (size_t)n * CHW;
#pragma unroll
        for (int mf = 0; mf < 4; mf++) {
            int o = mf * 16 + g;
            float b0 = B[o] * wscale, b1 = B[o + 8] * wscale;
#pragma unroll
            for (int nf = 0; nf < 4; nf++) {
                int p = p0 + wn + nf * 8 + 2 * tig;
                *(uint2*)(dst + o * HW + p) =
                    make_uint2(f2tf(acc[mf][nf][0] + b0), f2tf(acc[mf][nf][1] + b0));
                *(uint2*)(dst + (o + 8) * HW + p) =
                    make_uint2(f2tf(acc[mf][nf][2] + b1), f2tf(acc[mf][nf][3] + b1));
            }
        }
    } else {
        __syncthreads();
        float* T = (float*)Xs;   // [256 p][68]
#pragma unroll
        for (int mf = 0; mf < 4; mf++) {
            int o = mf * 16 + g;
            float b0 = B[o], b1 = B[o + 8];
#pragma unroll
            for (int nf = 0; nf < 4; nf++) {
                int p = wn + nf * 8 + 2 * tig;
                T[p * 68 + o]           = acc[mf][nf][0] + b0;
                T[(p + 1) * 68 + o]     = acc[mf][nf][1] + b0;
                T[p * 68 + o + 8]       = acc[mf][nf][2] + b1;
                T[(p + 1) * 68 + o + 8] = acc[mf][nf][3] + b1;
            }
        }
        __syncthreads();
        float* dst = g_kt + (size_t)n * CHW;
        for (int idx = tid; idx < 256 * 16; idx += 256) {
            int p = idx >> 4, c4 = (idx & 15) << 2;
            uint4 v = make_uint4(f2tf(T[p * 68 + c4]),     f2tf(T[p * 68 + c4 + 1]),
                                 f2tf(T[p * 68 + c4 + 2]), f2tf(T[p * 68 + c4 + 3]));
            *(uint4*)(dst + (size_t)(p0 + p) * C + c4) = v;
        }
    }
}

// ---------------- 3. flash (R10 shape) + ldmatrix a-fragments ----------------
// grid = (8 jt, NB), block 256 (8 warps = 2 i-groups x 4 j-groups of 32x32)
// smem u32: QP[64*136]=8704 (Q staging then Ps) | K0,K1,V0,V1[64*68]
//           | sums 256 | rcol 128   => 26496 u32 = 105984 B
#define OFF_QP  0
#define OFF_K0  8704
#define OFF_K1  (8704 + 4352)
#define OFF_V0  (8704 + 8704)
#define OFF_V1  (8704 + 8704 + 4352)
#define OFF_SUM (8704 + 8704 + 8704)
#define OFF_RC  (OFF_SUM + 256)
#define FLASH_U32 (OFF_RC + 128)

__global__ __launch_bounds__(256, 1) void flash_kernel(
    float* __restrict__ attn_out, float* __restrict__ xout)
{
    extern __shared__ unsigned fsm[];
    unsigned* Qs  = fsm + OFF_QP;
    unsigned* Ps  = fsm + OFF_QP;
    float*    sums = (float*)(fsm + OFF_SUM);
    float*    rcol = (float*)(fsm + OFF_RC);

    int n  = blockIdx.y;
    int j0 = blockIdx.x * JT;
    int tid = threadIdx.x;
    const float* kt = g_kt + (size_t)n * CHW;
    const float* qp = g_q  + (size_t)n * CHW;
    const float* vp = g_v  + (size_t)n * CHW;

    unsigned sb = (unsigned)__cvta_generic_to_shared(fsm);

    int li[4], lc[4];
#pragma unroll
    for (int t = 0; t < 4; t++) {
        int idx = tid + t * 256;
        li[t] = idx >> 4; lc[t] = (idx & 15) << 2;
    }

    // preload K chunk 0 (Phase A)
#pragma unroll
    for (int t = 0; t < 4; t++)
        cp16(sb + ((OFF_K0 + li[t] * 68 + lc[t]) << 2), kt + (size_t)li[t] * C + lc[t]);
    CP_COMMIT();

    // Q staging [64 c][128 j] (tf32 bits, pre-scaled)
    for (int idx = tid; idx < 64 * 32; idx += 256) {
        int c = idx >> 5, j4 = (idx & 31) << 2;
        *(uint4*)(Qs + c * 136 + j4) = *(const uint4*)(qp + c * HW + j0 + j4);
    }
    __syncthreads();

    int wid = tid >> 5, lane = tid & 31;
    int g = lane >> 2, tig = lane & 3;
    int wm = (wid & 1) * 32;         // i (mma1) / c (mma2) group
    int wj = (wid >> 1) * 32;        // j group

    // per-lane ldmatrix base (elements): tile = lane>>3
    // row = wm + mf*16 + ((lane>>3)&1)*8 + (lane&7); col4 = (lane>>4)*4
    unsigned abase[2];
#pragma unroll
    for (int mf = 0; mf < 2; mf++)
        abase[mf] = (unsigned)((wm + mf * 16 + ((lane >> 3) & 1) * 8 + (lane & 7)) * 68
                               + (lane >> 4) * 4);

    // Q fragments (64 regs)
    unsigned Qb[8][4][2];
#pragma unroll
    for (int kk = 0; kk < 8; kk++)
#pragma unroll
        for (int nf = 0; nf < 4; nf++) {
            int col = wj + nf * 8 + g;
            Qb[kk][nf][0] = Qs[(kk * 8 + tig) * 136 + col];
            Qb[kk][nf][1] = Qs[(kk * 8 + tig + 4) * 136 + col];
        }
    __syncthreads();   // Qs free for Ps reuse

    // ---------------- Phase A: column sums of exp2(logits) -------------------
    float s_run[4][2];
#pragma unroll
    for (int nf = 0; nf < 4; nf++) { s_run[nf][0] = 0.f; s_run[nf][1] = 0.f; }

    for (int ch = 0; ch < 16; ch++) {
        CP_WAIT0();
        __syncthreads();
        if (ch < 15) {
            int i0n = (ch + 1) * IC;
            unsigned koff = ((ch + 1) & 1) ? OFF_K1 : OFF_K0;
#pragma unroll
            for (int t = 0; t < 4; t++)
                cp16(sb + ((koff + li[t] * 68 + lc[t]) << 2),
                     kt + (size_t)(i0n + li[t]) * C + lc[t]);
            CP_COMMIT();
        }
        unsigned kbase = sb + (((ch & 1) ? OFF_K1 : OFF_K0) << 2);

        float acc1[2][4][4] = {};
#pragma unroll
        for (int kk = 0; kk < 8; kk++) {
            unsigned a[2][4];
#pragma unroll
            for (int mf = 0; mf < 2; mf++)
                ldsm4(a[mf], kbase + ((abase[mf] + kk * 8) << 2));
#pragma unroll
            for (int mf = 0; mf < 2; mf++)
#pragma unroll
                for (int nf = 0; nf < 4; nf++)
                    mma_tf32(acc1[mf][nf], a[mf], Qb[kk][nf]);
        }
#pragma unroll
        for (int mf = 0; mf < 2; mf++)
#pragma unroll
            for (int nf = 0; nf < 4; nf++) {
                s_run[nf][0] += ex2(acc1[mf][nf][0]) + ex2(acc1[mf][nf][2]);
                s_run[nf][1] += ex2(acc1[mf][nf][1]) + ex2(acc1[mf][nf][3]);
            }
    }

    // reduce over g-lanes, then across the 2 i-groups via smem
#pragma unroll
    for (int mask = 4; mask <= 16; mask <<= 1)
#pragma unroll
        for (int nf = 0; nf < 4; nf++)
#pragma unroll
            for (int par = 0; par < 2; par++)
                s_run[nf][par] += __shfl_xor_sync(0xFFFFFFFF, s_run[nf][par], mask);

    if (g == 0) {
#pragma unroll
        for (int nf = 0; nf < 4; nf++)
#pragma unroll
            for (int par = 0; par < 2; par++)
                sums[(wid & 1) * 128 + wj + nf * 8 + 2 * tig + par] = s_run[nf][par];
    }
    __syncthreads();
    if (tid < 128) rcol[tid] = 1.0f / (sums[tid] + sums[128 + tid]);

    // prefetch Phase B chunk 0 (K + V)
#pragma unroll
    for (int t = 0; t < 4; t++) {
        cp16(sb + ((OFF_K0 + li[t] * 68 + lc[t]) << 2), kt + (size_t)li[t] * C + lc[t]);
        cp16(sb + ((OFF_V0 + li[t] * 68 + lc[t]) << 2), vp + li[t] * HW + lc[t]);
    }
    CP_COMMIT();
    __syncthreads();

    float rj[4][2];
#pragma unroll
    for (int nf = 0; nf < 4; nf++)
#pragma unroll
        for (int par = 0; par < 2; par++)
            rj[nf][par] = rcol[wj + nf * 8 + 2 * tig + par];

    // ---------------- Phase B: normalized probs + V@P ------------------------
    float* ap = attn_out ? attn_out + (size_t)n * HW * HW + j0 : nullptr;
    float acc2[2][4][4] = {};

    for (int ch = 0; ch < 16; ch++) {
        CP_WAIT0();
        __syncthreads();
        if (ch < 15) {
            int i0n = (ch + 1) * IC;
            unsigned koff = ((ch + 1) & 1) ? OFF_K1 : OFF_K0;
            unsigned voff = ((ch + 1) & 1) ? OFF_V1 : OFF_V0;
#pragma unroll
            for (int t = 0; t < 4; t++) {
                cp16(sb + ((koff + li[t] * 68 + lc[t]) << 2),
                     kt + (size_t)(i0n + li[t]) * C + lc[t]);
                cp16(sb + ((voff + li[t] * 68 + lc[t]) << 2),
                     vp + li[t] * HW + i0n + lc[t]);
            }
            CP_COMMIT();
        }
        unsigned kbase = sb + (((ch & 1) ? OFF_K1 : OFF_K0) << 2);
        unsigned vbase = sb + (((ch & 1) ? OFF_V1 : OFF_V0) << 2);
        int i0 = ch * IC;

        float acc1[2][4][4] = {};
#pragma unroll
        for (int kk = 0; kk < 8; kk++) {
            unsigned a[2][4];
#pragma unroll
            for (int mf = 0; mf < 2; mf++)
                ldsm4(a[mf], kbase + ((abase[mf] + kk * 8) << 2));
#pragma unroll
            for (int mf = 0; mf < 2; mf++)
#pragma unroll
                for (int nf = 0; nf < 4; nf++)
                    mma_tf32(acc1[mf][nf], a[mf], Qb[kk][nf]);
        }

        // normalized probs: STG + STS(tf32)
#pragma unroll
        for (int mf = 0; mf < 2; mf++) {
            int il = wm + mf * 16 + g;
#pragma unroll
            for (int nf = 0; nf < 4; nf++) {
                int col = wj + nf * 8 + 2 * tig;
                float p0 = ex2(acc1[mf][nf][0]) * rj[nf][0];
                float p1 = ex2(acc1[mf][nf][1]) * rj[nf][1];
                float p2 = ex2(acc1[mf][nf][2]) * rj[nf][0];
                float p3 = ex2(acc1[mf][nf][3]) * rj[nf][1];
                if (ap) {
                    *(float2*)(ap + (size_t)(i0 + il) * HW + col)     = make_float2(p0, p1);
                    *(float2*)(ap + (size_t)(i0 + il + 8) * HW + col) = make_float2(p2, p3);
                }
                *(uint2*)(Ps + il * 136 + col)       = make_uint2(f2tf(p0), f2tf(p1));
                *(uint2*)(Ps + (il + 8) * 136 + col) = make_uint2(f2tf(p2), f2tf(p3));
            }
        }
        __syncthreads();   // Ps complete

        if (xout) {
#pragma unroll
            for (int kk = 0; kk < 8; kk++) {
                int k0 = kk * 8;
                unsigned a[2][4], b[4][2];
#pragma unroll
                for (int mf = 0; mf < 2; mf++)
                    ldsm4(a[mf], vbase + ((abase[mf] + k0) << 2));
#pragma unroll
                for (int nf = 0; nf < 4; nf++) {
                    int col = wj + nf * 8 + g;
                    b[nf][0] = Ps[(k0 + tig) * 136 + col];
                    b[nf][1] = Ps[(k0 + tig + 4) * 136 + col];
                }
#pragma unroll
                for (int mf = 0; mf < 2; mf++)
#pragma unroll
                    for (int nf = 0; nf < 4; nf++)
                        mma_tf32(acc2[mf][nf], a[mf], b[nf]);
            }
        }
    }

    if (!xout) return;
    const float* qn = g_qn + (size_t)n * CHW;
    float* xp = xout + (size_t)n * CHW;
#pragma unroll
    for (int mf = 0; mf < 2; mf++) {
        int c = wm + mf * 16 + g;
#pragma unroll
        for (int nf = 0; nf < 4; nf++) {
            int j = j0 + wj + nf * 8 + 2 * tig;
            float2 q0 = *(const float2*)(qn + c * HW + j);
            float2 q1 = *(const float2*)(qn + (c + 8) * HW + j);
            *(float2*)(xp + c * HW + j) =
                make_float2(acc2[mf][nf][0] + q0.x, acc2[mf][nf][1] + q0.y);
            *(float2*)(xp + (c + 8) * HW + j) =
                make_float2(acc2[mf][nf][2] + q1.x, acc2[mf][nf][3] + q1.y);
        }
    }
}

// ---------------------------------------------------------------------------
extern "C" void kernel_launch(void* const* d_in, const int* in_sizes, int n_in,
                              void* d_out, int out_size)
{
    const float* query = (const float*)d_in[0];
    const float* key   = (const float*)d_in[1];
    const float* value = (const float*)d_in[2];
    const float* ln1w  = (const float*)d_in[3];
    const float* ln1b  = (const float*)d_in[4];
    const float* ln2w  = (const float*)d_in[5];
    const float* ln2b  = (const float*)d_in[6];
    const float* ln3w  = (const float*)d_in[7];
    const float* ln3b  = (const float*)d_in[8];
    const float* wq    = (const float*)d_in[9];
    const float* bq    = (const float*)d_in[10];
    const float* wk    = (const float*)d_in[11];
    const float* bk    = (const float*)d_in[12];
    const float* wv    = (const float*)d_in[13];
    const float* bv    = (const float*)d_in[14];

    float* out = (float*)d_out;
    const size_t XSZ = (size_t)NB * CHW;
    const size_t ASZ = (size_t)NB * HW * HW;

    float* x_out    = nullptr;
    float* attn_out = nullptr;
    size_t osz = (size_t)out_size;
    if (osz >= XSZ + ASZ)      { x_out = out; attn_out = out + XSZ; }
    else if (osz == ASZ)       { attn_out = out; }
    else                       { x_out = out; }

    static int attr_set = 0;
    const int PROJ_SMEM  = (64 * 68 + 256 * 68) * 4;   // 87040
    const int FLASH_SMEM = FLASH_U32 * 4;              // 105984
    if (!attr_set) {
        cudaFuncSetAttribute(proj_kernel,
                             cudaFuncAttributeMaxDynamicSharedMemorySize, PROJ_SMEM);
        cudaFuncSetAttribute(flash_kernel,
                             cudaFuncAttributeMaxDynamicSharedMemorySize, FLASH_SMEM);
        attr_set = 1;
    }

    ln_stats_kernel<<<dim3(96, 4), 256>>>(query, key, value);
    ln_apply_q_kernel<<<dim3(NB, 4), 256>>>(query, ln1w, ln1b);
    proj_kernel<<<dim3(4, NB, 3), 256, PROJ_SMEM>>>(key, value, wq, bq, wk, bk, wv, bv,
                                                    ln2w, ln2b, ln3w, ln3b);
    flash_kernel<<<dim3(HW / JT, NB), 256, FLASH_SMEM>>>(attn_out, x_out);
}

// round 14
// speedup vs baseline: 1.8010x; 1.4628x over previous
#include <cuda_runtime.h>
#include <cuda_fp16.h>
#include <math_constants.h>

#define NB  32
#define C   64
#define HW  1024
#define CHW 65536
#define EPS 1e-5f
#define JT  128
#define IC  64
#define LSCALE 0.180336880f   // 0.125 * log2(e)

// ---------------- scratch ----------------------------------------------------
__device__ float  g_qn[NB * CHW];          // fp32 normalized query (residual)
__device__ __half g_q [NB * CHW];          // fp16, pre-scaled by LSCALE, [c][j]
__device__ __half g_kt[NB * CHW];          // fp16, K transposed [i][c]
__device__ __half g_v [NB * CHW];          // fp16, [c][i]
__device__ float  g_part[96][4][2];        // LN partial sums

// ---------------- helpers ----------------------------------------------------
__device__ __forceinline__ unsigned f2tf(float x) {
    unsigned u;
    asm("cvt.rna.tf32.f32 %0, %1;" : "=r"(u) : "f"(x));
    return u;
}
__device__ __forceinline__ float ex2(float x) {
    float y;
    asm("ex2.approx.f32 %0, %1;" : "=f"(y) : "f"(x));
    return y;
}
__device__ __forceinline__ void mma_tf32(float* d, const unsigned* a, const unsigned* b) {
    asm volatile(
        "mma.sync.aligned.m16n8k8.row.col.f32.tf32.tf32.f32 "
        "{%0,%1,%2,%3}, {%4,%5,%6,%7}, {%8,%9}, {%0,%1,%2,%3};\n"
        : "+f"(d[0]), "+f"(d[1]), "+f"(d[2]), "+f"(d[3])
        : "r"(a[0]), "r"(a[1]), "r"(a[2]), "r"(a[3]), "r"(b[0]), "r"(b[1]));
}
__device__ __forceinline__ void mma_f16(float* d, const unsigned* a, const unsigned* b) {
    asm volatile(
        "mma.sync.aligned.m16n8k16.row.col.f32.f16.f16.f32 "
        "{%0,%1,%2,%3}, {%4,%5,%6,%7}, {%8,%9}, {%0,%1,%2,%3};\n"
        : "+f"(d[0]), "+f"(d[1]), "+f"(d[2]), "+f"(d[3])
        : "r"(a[0]), "r"(a[1]), "r"(a[2]), "r"(a[3]), "r"(b[0]), "r"(b[1]));
}
__device__ __forceinline__ void ldsm4(unsigned* r, unsigned addr) {
    asm volatile("ldmatrix.sync.aligned.m8n8.x4.shared.b16 {%0,%1,%2,%3}, [%4];"
        : "=r"(r[0]), "=r"(r[1]), "=r"(r[2]), "=r"(r[3]) : "r"(addr));
}
__device__ __forceinline__ void ldsm4t(unsigned* r, unsigned addr) {
    asm volatile("ldmatrix.sync.aligned.m8n8.x4.trans.shared.b16 {%0,%1,%2,%3}, [%4];"
        : "=r"(r[0]), "=r"(r[1]), "=r"(r[2]), "=r"(r[3]) : "r"(addr));
}
__device__ __forceinline__ void cp16(unsigned dst, const void* src) {
    asm volatile("cp.async.cg.shared.global [%0], [%1], 16;" :: "r"(dst), "l"(src));
}
#define CP_COMMIT() asm volatile("cp.async.commit_group;")
#define CP_WAIT0()  asm volatile("cp.async.wait_group 0;")

// ---------------- 1a. LN stats: grid (96, 4), 256 thr -----------------------
__global__ __launch_bounds__(256) void ln_stats_kernel(
    const float* __restrict__ q, const float* __restrict__ k, const float* __restrict__ v)
{
    int t     = blockIdx.x;
    int quart = blockIdx.y;
    int which = t % 3, n = t / 3;
    const float* x = (which == 0 ? q : which == 1 ? k : v) + (size_t)n * CHW + quart * 16384;

    int tid = threadIdx.x;
    float4 a4 = make_float4(0, 0, 0, 0), q4 = make_float4(0, 0, 0, 0);
    for (int i = tid * 4; i < 16384; i += 256 * 4) {
        float4 val = *(const float4*)(x + i);
        a4.x += val.x; a4.y += val.y; a4.z += val.z; a4.w += val.w;
        q4.x += val.x * val.x; q4.y += val.y * val.y;
        q4.z += val.z * val.z; q4.w += val.w * val.w;
    }
    float s  = a4.x + a4.y + a4.z + a4.w;
    float ss = q4.x + q4.y + q4.z + q4.w;

    __shared__ float sm[256], sm2[256];
    sm[tid] = s; sm2[tid] = ss;
    __syncthreads();
    for (int o = 128; o > 0; o >>= 1) {
        if (tid < o) { sm[tid] += sm[tid + o]; sm2[tid] += sm2[tid + o]; }
        __syncthreads();
    }
    if (tid == 0) { g_part[t][quart][0] = sm[0]; g_part[t][quart][1] = sm2[0]; }
}

// ---------------- 1b. LN apply (query only): grid (NB, 4) -------------------
__global__ __launch_bounds__(256) void ln_apply_q_kernel(
    const float* __restrict__ q,
    const float* __restrict__ w1, const float* __restrict__ b1)
{
    int n     = blockIdx.x;
    int quart = blockIdx.y;
    int t     = n * 3;
    size_t off = (size_t)n * CHW + quart * 16384;
    const float* x = q + off;
    float* dst = g_qn + off;
    const float* w = w1 + quart * 16384;
    const float* b = b1 + quart * 16384;

    float s = 0.f, ss = 0.f;
#pragma unroll
    for (int qq = 0; qq < 4; qq++) { s += g_part[t][qq][0]; ss += g_part[t][qq][1]; }
    float mean = s * (1.0f / CHW);
    float var  = ss * (1.0f / CHW) - mean * mean;
    float rstd = rsqrtf(var + EPS);

    int tid = threadIdx.x;
    for (int i = tid * 4; i < 16384; i += 256 * 4) {
        float4 val = *(const float4*)(x + i);
        float4 wv  = *(const float4*)(w + i);
        float4 bv  = *(const float4*)(b + i);
        float4 o4;
        o4.x = (val.x - mean) * rstd * wv.x + bv.x;
        o4.y = (val.y - mean) * rstd * wv.y + bv.y;
        o4.z = (val.z - mean) * rstd * wv.z + bv.z;
        o4.w = (val.w - mean) * rstd * wv.w + bv.w;
        *(float4*)(dst + i) = o4;
    }
}

// ---------------- 2. projection (LN fused for K/V); fp16 outputs ------------
__global__ __launch_bounds__(256) void proj_kernel(
    const float* __restrict__ key, const float* __restrict__ value,
    const float* __restrict__ wq, const float* __restrict__ bq,
    const float* __restrict__ wk, const float* __restrict__ bk,
    const float* __restrict__ wv, const float* __restrict__ bv,
    const float* __restrict__ ln2w, const float* __restrict__ ln2b,
    const float* __restrict__ ln3w, const float* __restrict__ ln3b)
{
    extern __shared__ unsigned psm[];
    unsigned* Ws = psm;              // [64 o][68]
    unsigned* Xs = psm + 64 * 68;    // [64 c][264]; T reuse needs 256*68

    int which = blockIdx.z;
    int n     = blockIdx.y;
    int p0    = blockIdx.x * 256;
    const float *W, *B;
    if (which == 0)      { W = wq; B = bq; }
    else if (which == 1) { W = wk; B = bk; }
    else                 { W = wv; B = bv; }
    float wscale = (which == 0) ? LSCALE : 1.0f;

    int tid = threadIdx.x;
    for (int idx = tid; idx < 64 * 16; idx += 256) {
        int o = idx >> 4, c4 = (idx & 15) << 2;
        float4 v = *(const float4*)(W + o * C + c4);
        *(uint4*)(Ws + o * 68 + c4) =
            make_uint4(f2tf(v.x * wscale), f2tf(v.y * wscale),
                       f2tf(v.z * wscale), f2tf(v.w * wscale));
    }

    if (which == 0) {
        const float* src = g_qn + (size_t)n * CHW;
        for (int idx = tid; idx < 64 * 64; idx += 256) {
            int c = idx >> 6, p4 = (idx & 63) << 2;
            float4 v = *(const float4*)(src + c * HW + p0 + p4);
            *(uint4*)(Xs + c * 264 + p4) =
                make_uint4(f2tf(v.x), f2tf(v.y), f2tf(v.z), f2tf(v.w));
        }
    } else {
        const float* raw = (which == 1 ? key : value) + (size_t)n * CHW;
        const float* lw  = (which == 1 ? ln2w : ln3w);
        const float* lb  = (which == 1 ? ln2b : ln3b);
        int t = n * 3 + which;
        float s = 0.f, ss = 0.f;
#pragma unroll
        for (int qq = 0; qq < 4; qq++) { s += g_part[t][qq][0]; ss += g_part[t][qq][1]; }
        float mean = s * (1.0f / CHW);
        float var  = ss * (1.0f / CHW) - mean * mean;
        float rstd = rsqrtf(var + EPS);
        for (int idx = tid; idx < 64 * 64; idx += 256) {
            int c = idx >> 6, p4 = (idx & 63) << 2;
            float4 xv = *(const float4*)(raw + c * HW + p0 + p4);
            float4 wv = *(const float4*)(lw  + c * HW + p0 + p4);
            float4 bv = *(const float4*)(lb  + c * HW + p0 + p4);
            float4 v;
            v.x = (xv.x - mean) * rstd * wv.x + bv.x;
            v.y = (xv.y - mean) * rstd * wv.y + bv.y;
            v.z = (xv.z - mean) * rstd * wv.z + bv.z;
            v.w = (xv.w - mean) * rstd * wv.w + bv.w;
            *(uint4*)(Xs + c * 264 + p4) =
                make_uint4(f2tf(v.x), f2tf(v.y), f2tf(v.z), f2tf(v.w));
        }
    }
    __syncthreads();

    int wid = tid >> 5, lane = tid & 31;
    int g = lane >> 2, tig = lane & 3;
    int wn = wid * 32;

    float acc[4][4][4] = {};
#pragma unroll
    for (int kk = 0; kk < 8; kk++) {
        int c0 = kk * 8;
        unsigned a[4][4], b[4][2];
#pragma unroll
        for (int mf = 0; mf < 4; mf++) {
            int r = mf * 16 + g;
            a[mf][0] = Ws[r * 68 + c0 + tig];
            a[mf][1] = Ws[(r + 8) * 68 + c0 + tig];
            a[mf][2] = Ws[r * 68 + c0 + tig + 4];
            a[mf][3] = Ws[(r + 8) * 68 + c0 + tig + 4];
        }
#pragma unroll
        for (int nf = 0; nf < 4; nf++) {
            int col = wn + nf * 8 + g;
            b[nf][0] = Xs[(c0 + tig) * 264 + col];
            b[nf][1] = Xs[(c0 + tig + 4) * 264 + col];
        }
#pragma unroll
        for (int mf = 0; mf < 4; mf++)
#pragma unroll
            for (int nf = 0; nf < 4; nf++)
                mma_tf32(acc[mf][nf], a[mf], b[nf]);
    }

    if (which != 1) {
        __half* dst = (which == 0 ? g_q : g_v) + (size_t)n * CHW;
#pragma unroll
        for (int mf = 0; mf < 4; mf++) {
            int o = mf * 16 + g;
            float b0 = B[o] * wscale, b1 = B[o + 8] * wscale;
#pragma unroll
            for (int nf = 0; nf < 4; nf++) {
                int p = p0 + wn + nf * 8 + 2 * tig;
                *(__half2*)(dst + o * HW + p) =
                    __floats2half2_rn(acc[mf][nf][0] + b0, acc[mf][nf][1] + b0);
                *(__half2*)(dst + (o + 8) * HW + p) =
                    __floats2half2_rn(acc[mf][nf][2] + b1, acc[mf][nf][3] + b1);
            }
        }
    } else {
        __syncthreads();
        float* T = (float*)Xs;   // [256 p][68]
#pragma unroll
        for (int mf = 0; mf < 4; mf++) {
            int o = mf * 16 + g;
            float b0 = B[o], b1 = B[o + 8];
#pragma unroll
            for (int nf = 0; nf < 4; nf++) {
                int p = wn + nf * 8 + 2 * tig;
                T[p * 68 + o]           = acc[mf][nf][0] + b0;
                T[(p + 1) * 68 + o]     = acc[mf][nf][1] + b0;
                T[p * 68 + o + 8]       = acc[mf][nf][2] + b1;
                T[(p + 1) * 68 + o + 8] = acc[mf][nf][3] + b1;
            }
        }
        __syncthreads();
        __half* dst = g_kt + (size_t)n * CHW;
        for (int idx = tid; idx < 256 * 16; idx += 256) {
            int p = idx >> 4, c4 = (idx & 15) << 2;
            __half2* d2 = (__half2*)(dst + (size_t)(p0 + p) * C + c4);
            d2[0] = __floats2half2_rn(T[p * 68 + c4],     T[p * 68 + c4 + 1]);
            d2[1] = __floats2half2_rn(T[p * 68 + c4 + 2], T[p * 68 + c4 + 3]);
        }
    }
}

// ---------------- 3. flash fp16: ldmatrix both operands, 2 CTA/SM -----------
// grid = (8 jt, NB), block 256 (8 warps = 2 i-groups x 4 j-groups of 32x32)
// smem (halves): Q[64][136] | K0,K1[64][72] | V0,V1[64][72] | P[64][136]
//   + fp32 sums[256], rcol[128]  => 73216 B  (2 CTAs/SM)
#define H_Q   0
#define H_K0  8704
#define H_K1  (8704 + 4608)
#define H_V0  (8704 + 9216)
#define H_V1  (8704 + 13824)
#define H_P   (8704 + 18432)
#define U_SUM 17920              // u32 offset (after 35840 halves)
#define U_RC  (U_SUM + 256)
#define FLASH_BYTES ((U_RC + 128) * 4)   // 73216

__global__ __launch_bounds__(256, 2) void flash_kernel(
    float* __restrict__ attn_out, float* __restrict__ xout)
{
    extern __shared__ unsigned fsm[];
    __half* hsm  = (__half*)fsm;
    float*  sums = (float*)(fsm + U_SUM);
    float*  rcol = (float*)(fsm + U_RC);

    int n  = blockIdx.y;
    int j0 = blockIdx.x * JT;
    int tid = threadIdx.x;
    const __half* kt = g_kt + (size_t)n * CHW;
    const __half* qp = g_q  + (size_t)n * CHW;
    const __half* vp = g_v  + (size_t)n * CHW;

    unsigned sb = (unsigned)__cvta_generic_to_shared(fsm);

    // K/V chunk load indices: 512 16B units = [64 rows][8x 8-half units]
    int li[2], lc[2];
#pragma unroll
    for (int t = 0; t < 2; t++) {
        int idx = tid + t * 256;
        li[t] = idx >> 3; lc[t] = (idx & 7) * 8;
    }

    // Q tile load: 1024 16B units = [64 rows][16x 8-half units]
#pragma unroll
    for (int t = 0; t < 4; t++) {
        int idx = tid + t * 256;
        int qr = idx >> 4, qc = (idx & 15) * 8;
        cp16(sb + (H_Q + qr * 136 + qc) * 2, qp + qr * HW + j0 + qc);
    }
    // preload K chunk 0
#pragma unroll
    for (int t = 0; t < 2; t++)
        cp16(sb + (H_K0 + li[t] * 72 + lc[t]) * 2, kt + (size_t)li[t] * C + lc[t]);
    CP_COMMIT();

    int wid = tid >> 5, lane = tid & 31;
    int g = lane >> 2, tig = lane & 3;
    int wm = (wid & 1) * 32;         // i (mma1) / c (mma2) group
    int wj = (wid >> 1) * 32;        // j group

    // ldmatrix per-lane offsets (bytes, before buffer base)
    int arow  = ((lane >> 3) & 1) * 8 + (lane & 7);
    int ahoff = (lane >> 4) * 8;
    unsigned kfo[2], qfo[2];
#pragma unroll
    for (int mf = 0; mf < 2; mf++)
        kfo[mf] = (unsigned)(((wm + mf * 16 + arow) * 72 + ahoff) * 2);
#pragma unroll
    for (int nn2 = 0; nn2 < 2; nn2++)
        qfo[nn2] = (unsigned)((arow * 136 + wj + nn2 * 16 + ahoff) * 2);

    unsigned qbase = sb + H_Q * 2;
    unsigned pbase = sb + H_P * 2;

    // ---------------- Phase A: column sums of exp2(logits) -------------------
    float s_run[4][2];
#pragma unroll
    for (int nf = 0; nf < 4; nf++) { s_run[nf][0] = 0.f; s_run[nf][1] = 0.f; }

    for (int ch = 0; ch < 16; ch++) {
        CP_WAIT0();
        __syncthreads();
        if (ch < 15) {
            int i0n = (ch + 1) * IC;
            unsigned koff = ((ch + 1) & 1) ? H_K1 : H_K0;
#pragma unroll
            for (int t = 0; t < 2; t++)
                cp16(sb + (koff + li[t] * 72 + lc[t]) * 2,
                     kt + (size_t)(i0n + li[t]) * C + lc[t]);
            CP_COMMIT();
        }
        unsigned kbase = sb + (((ch & 1) ? H_K1 : H_K0) * 2);

        float acc1[2][4][4] = {};
#pragma unroll
        for (int kk = 0; kk < 4; kk++) {
            unsigned a[2][4], qb[2][4];
#pragma unroll
            for (int mf = 0; mf < 2; mf++)
                ldsm4(a[mf], kbase + kfo[mf] + kk * 32);
#pragma unroll
            for (int nn2 = 0; nn2 < 2; nn2++)
                ldsm4t(qb[nn2], qbase + qfo[nn2] + kk * 4352);
#pragma unroll
            for (int mf = 0; mf < 2; mf++) {
                mma_f16(acc1[mf][0], a[mf], qb[0] + 0);
                mma_f16(acc1[mf][1], a[mf], qb[0] + 2);
                mma_f16(acc1[mf][2], a[mf], qb[1] + 0);
                mma_f16(acc1[mf][3], a[mf], qb[1] + 2);
            }
        }
#pragma unroll
        for (int mf = 0; mf < 2; mf++)
#pragma unroll
            for (int nf = 0; nf < 4; nf++) {
                s_run[nf][0] += ex2(acc1[mf][nf][0]) + ex2(acc1[mf][nf][2]);
                s_run[nf][1] += ex2(acc1[mf][nf][1]) + ex2(acc1[mf][nf][3]);
            }
    }

    // reduce over g-lanes, then across the 2 i-groups via smem
#pragma unroll
    for (int mask = 4; mask <= 16; mask <<= 1)
#pragma unroll
        for (int nf = 0; nf < 4; nf++)
#pragma unroll
            for (int par = 0; par < 2; par++)
                s_run[nf][par] += __shfl_xor_sync(0xFFFFFFFF, s_run[nf][par], mask);

    if (g == 0) {
#pragma unroll
        for (int nf = 0; nf < 4; nf++)
#pragma unroll
            for (int par = 0; par < 2; par++)
                sums[(wid & 1) * 128 + wj + nf * 8 + 2 * tig + par] = s_run[nf][par];
    }
    __syncthreads();
    if (tid < 128) rcol[tid] = 1.0f / (sums[tid] + sums[128 + tid]);

    // prefetch Phase B chunk 0 (K + V)
#pragma unroll
    for (int t = 0; t < 2; t++) {
        cp16(sb + (H_K0 + li[t] * 72 + lc[t]) * 2, kt + (size_t)li[t] * C + lc[t]);
        cp16(sb + (H_V0 + li[t] * 72 + lc[t]) * 2, vp + li[t] * HW + lc[t]);
    }
    CP_COMMIT();
    __syncthreads();

    float rj[4][2];
#pragma unroll
    for (int nf = 0; nf < 4; nf++)
#pragma unroll
        for (int par = 0; par < 2; par++)
            rj[nf][par] = rcol[wj + nf * 8 + 2 * tig + par];

    // ---------------- Phase B: normalized probs + V@P ------------------------
    float* ap = attn_out ? attn_out + (size_t)n * HW * HW + j0 : nullptr;
    float acc2[2][4][4] = {};

    for (int ch = 0; ch < 16; ch++) {
        CP_WAIT0();
        __syncthreads();
        if (ch < 15) {
            int i0n = (ch + 1) * IC;
            unsigned koff = ((ch + 1) & 1) ? H_K1 : H_K0;
            unsigned voff = ((ch + 1) & 1) ? H_V1 : H_V0;
#pragma unroll
            for (int t = 0; t < 2; t++) {
                cp16(sb + (koff + li[t] * 72 + lc[t]) * 2,
                     kt + (size_t)(i0n + li[t]) * C + lc[t]);
                cp16(sb + (voff + li[t] * 72 + lc[t]) * 2,
                     vp + li[t] * HW + i0n + lc[t]);
            }
            CP_COMMIT();
        }
        unsigned kbase = sb + (((ch & 1) ? H_K1 : H_K0) * 2);
        unsigned vbase = sb + (((ch & 1) ? H_V1 : H_V0) * 2);
        int i0 = ch * IC;

        float acc1[2][4][4] = {};
#pragma unroll
        for (int kk = 0; kk < 4; kk++) {
            unsigned a[2][4], qb[2][4];
#pragma unroll
            for (int mf = 0; mf < 2; mf++)
                ldsm4(a[mf], kbase + kfo[mf] + kk * 32);
#pragma unroll
            for (int nn2 = 0; nn2 < 2; nn2++)
                ldsm4t(qb[nn2], qbase + qfo[nn2] + kk * 4352);
#pragma unroll
            for (int mf = 0; mf < 2; mf++) {
                mma_f16(acc1[mf][0], a[mf], qb[0] + 0);
                mma_f16(acc1[mf][1], a[mf], qb[0] + 2);
                mma_f16(acc1[mf][2], a[mf], qb[1] + 0);
                mma_f16(acc1[mf][3], a[mf], qb[1] + 2);
            }
        }

        // normalized probs: fp32 STG + fp16 STS
#pragma unroll
        for (int mf = 0; mf < 2; mf++) {
            int il = wm + mf * 16 + g;
#pragma unroll
            for (int nf = 0; nf < 4; nf++) {
                int col = wj + nf * 8 + 2 * tig;
                float p0 = ex2(acc1[mf][nf][0]) * rj[nf][0];
                float p1 = ex2(acc1[mf][nf][1]) * rj[nf][1];
                float p2 = ex2(acc1[mf][nf][2]) * rj[nf][0];
                float p3 = ex2(acc1[mf][nf][3]) * rj[nf][1];
                if (ap) {
                    *(float2*)(ap + (size_t)(i0 + il) * HW + col)     = make_float2(p0, p1);
                    *(float2*)(ap + (size_t)(i0 + il + 8) * HW + col) = make_float2(p2, p3);
                }
                *(__half2*)(hsm + H_P + il * 136 + col)       = __floats2half2_rn(p0, p1);
                *(__half2*)(hsm + H_P + (il + 8) * 136 + col) = __floats2half2_rn(p2, p3);
            }
        }
        __syncthreads();   // Ps complete

        if (xout) {
#pragma unroll
            for (int kk = 0; kk < 4; kk++) {
                unsigned a[2][4], pb[2][4];
#pragma unroll
                for (int mf = 0; mf < 2; mf++)
                    ldsm4(a[mf], vbase + kfo[mf] + kk * 32);
#pragma unroll
                for (int nn2 = 0; nn2 < 2; nn2++)
                    ldsm4t(pb[nn2], pbase + qfo[nn2] + kk * 4352);
#pragma unroll
                for (int mf = 0; mf < 2; mf++) {
                    mma_f16(acc2[mf][0], a[mf], pb[0] + 0);
                    mma_f16(acc2[mf][1], a[mf], pb[0] + 2);
                    mma_f16(acc2[mf][2], a[mf], pb[1] + 0);
                    mma_f16(acc2[mf][3], a[mf], pb[1] + 2);
                }
            }
        }
    }

    if (!xout) return;
    const float* qn = g_qn + (size_t)n * CHW;
    float* xp = xout + (size_t)n * CHW;
#pragma unroll
    for (int mf = 0; mf < 2; mf++) {
        int c = wm + mf * 16 + g;
#pragma unroll
        for (int nf = 0; nf < 4; nf++) {
            int j = j0 + wj + nf * 8 + 2 * tig;
            float2 q0 = *(const float2*)(qn + c * HW + j);
            float2 q1 = *(const float2*)(qn + (c + 8) * HW + j);
            *(float2*)(xp + c * HW + j) =
                make_float2(acc2[mf][nf][0] + q0.x, acc2[mf][nf][1] + q0.y);
            *(float2*)(xp + (c + 8) * HW + j) =
                make_float2(acc2[mf][nf][2] + q1.x, acc2[mf][nf][3] + q1.y);
        }
    }
}

// ---------------------------------------------------------------------------
extern "C" void kernel_launch(void* const* d_in, const int* in_sizes, int n_in,
                              void* d_out, int out_size)
{
    const float* query = (const float*)d_in[0];
    const float* key   = (const float*)d_in[1];
    const float* value = (const float*)d_in[2];
    const float* ln1w  = (const float*)d_in[3];
    const float* ln1b  = (const float*)d_in[4];
    const float* ln2w  = (const float*)d_in[5];
    const float* ln2b  = (const float*)d_in[6];
    const float* ln3w  = (const float*)d_in[7];
    const float* ln3b  = (const float*)d_in[8];
    const float* wq    = (const float*)d_in[9];
    const float* bq    = (const float*)d_in[10];
    const float* wk    = (const float*)d_in[11];
    const float* bk    = (const float*)d_in[12];
    const float* wv    = (const float*)d_in[13];
    const float* bv    = (const float*)d_in[14];

    float* out = (float*)d_out;
    const size_t XSZ = (size_t)NB * CHW;
    const size_t ASZ = (size_t)NB * HW * HW;

    float* x_out    = nullptr;
    float* attn_out = nullptr;
    size_t osz = (size_t)out_size;
    if (osz >= XSZ + ASZ)      { x_out = out; attn_out = out + XSZ; }
    else if (osz == ASZ)       { attn_out = out; }
    else                       { x_out = out; }

    static int attr_set = 0;
    const int PROJ_SMEM = (64 * 68 + 256 * 68) * 4;   // 87040
    if (!attr_set) {
        cudaFuncSetAttribute(proj_kernel,
                             cudaFuncAttributeMaxDynamicSharedMemorySize, PROJ_SMEM);
        cudaFuncSetAttribute(flash_kernel,
                             cudaFuncAttributeMaxDynamicSharedMemorySize, FLASH_BYTES);
        attr_set = 1;
    }

    ln_stats_kernel<<<dim3(96, 4), 256>>>(query, key, value);
    ln_apply_q_kernel<<<dim3(NB, 4), 256>>>(query, ln1w, ln1b);
    proj_kernel<<<dim3(4, NB, 3), 256, PROJ_SMEM>>>(key, value, wq, bq, wk, bk, wv, bv,
                                                    ln2w, ln2b, ln3w, ln3b);
    flash_kernel<<<dim3(HW / JT, NB), 256, FLASH_BYTES>>>(attn_out, x_out);
}

// round 15
// speedup vs baseline: 1.8988x; 1.0543x over previous
#include <cuda_runtime.h>
#include <cuda_fp16.h>
#include <math_constants.h>

#define NB  32
#define C   64
#define HW  1024
#define CHW 65536
#define EPS 1e-5f
#define JT  128
#define IC  64
#define LSCALE 0.180336880f   // 0.125 * log2(e)

// ---------------- scratch ----------------------------------------------------
__device__ float  g_qn[NB * CHW];          // fp32 normalized query (residual)
__device__ __half g_q [NB * CHW];          // fp16, pre-scaled by LSCALE, [c][j]
__device__ __half g_kt[NB * CHW];          // fp16, K transposed [i][c]
__device__ __half g_v [NB * CHW];          // fp16, [c][i]
__device__ float  g_part[96][4][2];        // LN partial sums

// ---------------- helpers ----------------------------------------------------
__device__ __forceinline__ float ex2(float x) {
    float y;
    asm("ex2.approx.f32 %0, %1;" : "=f"(y) : "f"(x));
    return y;
}
__device__ __forceinline__ void mma_f16(float* d, const unsigned* a, const unsigned* b) {
    asm volatile(
        "mma.sync.aligned.m16n8k16.row.col.f32.f16.f16.f32 "
        "{%0,%1,%2,%3}, {%4,%5,%6,%7}, {%8,%9}, {%0,%1,%2,%3};\n"
        : "+f"(d[0]), "+f"(d[1]), "+f"(d[2]), "+f"(d[3])
        : "r"(a[0]), "r"(a[1]), "r"(a[2]), "r"(a[3]), "r"(b[0]), "r"(b[1]));
}
__device__ __forceinline__ void ldsm4(unsigned* r, unsigned addr) {
    asm volatile("ldmatrix.sync.aligned.m8n8.x4.shared.b16 {%0,%1,%2,%3}, [%4];"
        : "=r"(r[0]), "=r"(r[1]), "=r"(r[2]), "=r"(r[3]) : "r"(addr));
}
__device__ __forceinline__ void ldsm4t(unsigned* r, unsigned addr) {
    asm volatile("ldmatrix.sync.aligned.m8n8.x4.trans.shared.b16 {%0,%1,%2,%3}, [%4];"
        : "=r"(r[0]), "=r"(r[1]), "=r"(r[2]), "=r"(r[3]) : "r"(addr));
}
__device__ __forceinline__ void cp16(unsigned dst, const void* src) {
    asm volatile("cp.async.cg.shared.global [%0], [%1], 16;" :: "r"(dst), "l"(src));
}
#define CP_COMMIT() asm volatile("cp.async.commit_group;")
#define CP_WAIT0()  asm volatile("cp.async.wait_group 0;")

// ---------------- 1. LN stats: grid (96, 4), 256 thr ------------------------
__global__ __launch_bounds__(256) void ln_stats_kernel(
    const float* __restrict__ q, const float* __restrict__ k, const float* __restrict__ v)
{
    int t     = blockIdx.x;
    int quart = blockIdx.y;
    int which = t % 3, n = t / 3;
    const float* x = (which == 0 ? q : which == 1 ? k : v) + (size_t)n * CHW + quart * 16384;

    int tid = threadIdx.x;
    float4 a4 = make_float4(0, 0, 0, 0), q4 = make_float4(0, 0, 0, 0);
    for (int i = tid * 4; i < 16384; i += 256 * 4) {
        float4 val = *(const float4*)(x + i);
        a4.x += val.x; a4.y += val.y; a4.z += val.z; a4.w += val.w;
        q4.x += val.x * val.x; q4.y += val.y * val.y;
        q4.z += val.z * val.z; q4.w += val.w * val.w;
    }
    float s  = a4.x + a4.y + a4.z + a4.w;
    float ss = q4.x + q4.y + q4.z + q4.w;

    __shared__ float sm[256], sm2[256];
    sm[tid] = s; sm2[tid] = ss;
    __syncthreads();
    for (int o = 128; o > 0; o >>= 1) {
        if (tid < o) { sm[tid] += sm[tid + o]; sm2[tid] += sm2[tid + o]; }
        __syncthreads();
    }
    if (tid == 0) { g_part[t][quart][0] = sm[0]; g_part[t][quart][1] = sm2[0]; }
}

// ---------------- 2. projection fp16 mma; LN fused for ALL three ------------
// grid = (4 pt, NB, 3), block 256. Tile M=64(o) N=256(p) K=64(c), 4 k16 steps
// smem halves: Wh[64][72]=4608 | Xh[64][264]=16896  (43008 B)
// K path reuses whole buffer as T fp32 [256][68] = 69632 B  -> PROJ_SMEM
#define PW_STR 72
#define PX_STR 264
#define PROJ_SMEM 69632
__global__ __launch_bounds__(256) void proj_kernel(
    const float* __restrict__ query, const float* __restrict__ key,
    const float* __restrict__ value,
    const float* __restrict__ wq, const float* __restrict__ bq,
    const float* __restrict__ wk, const float* __restrict__ bk,
    const float* __restrict__ wv, const float* __restrict__ bv,
    const float* __restrict__ ln1w, const float* __restrict__ ln1b,
    const float* __restrict__ ln2w, const float* __restrict__ ln2b,
    const float* __restrict__ ln3w, const float* __restrict__ ln3b)
{
    extern __shared__ __half ph[];
    __half* Wh = ph;
    __half* Xh = ph + 4608;

    int which = blockIdx.z;
    int n     = blockIdx.y;
    int p0    = blockIdx.x * 256;
    const float *W, *B, *raw, *lw, *lb;
    if (which == 0)      { W = wq; B = bq; raw = query; lw = ln1w; lb = ln1b; }
    else if (which == 1) { W = wk; B = bk; raw = key;   lw = ln2w; lb = ln2b; }
    else                 { W = wv; B = bv; raw = value; lw = ln3w; lb = ln3b; }
    float wscale = (which == 0) ? LSCALE : 1.0f;
    raw += (size_t)n * CHW;

    int t = n * 3 + which;
    float s = 0.f, ss = 0.f;
#pragma unroll
    for (int qq = 0; qq < 4; qq++) { s += g_part[t][qq][0]; ss += g_part[t][qq][1]; }
    float mean = s * (1.0f / CHW);
    float var  = ss * (1.0f / CHW) - mean * mean;
    float rstd = rsqrtf(var + EPS);

    int tid = threadIdx.x;
    // stage W (fp16, wscale folded)
    for (int idx = tid; idx < 64 * 16; idx += 256) {
        int o = idx >> 4, c4 = (idx & 15) << 2;
        float4 v = *(const float4*)(W + o * C + c4);
        __half2 h0 = __floats2half2_rn(v.x * wscale, v.y * wscale);
        __half2 h1 = __floats2half2_rn(v.z * wscale, v.w * wscale);
        *(uint2*)(Wh + o * PW_STR + c4) = make_uint2(
            *(unsigned*)&h0, *(unsigned*)&h1);
    }
    // stage X = LN(raw) (fp16); for which==0 also write g_qn fp32
    float* gqn = g_qn + (size_t)n * CHW;
    for (int idx = tid; idx < 64 * 64; idx += 256) {
        int c = idx >> 6, p4 = (idx & 63) << 2;
        float4 xv = *(const float4*)(raw + c * HW + p0 + p4);
        float4 wv = *(const float4*)(lw  + c * HW + p0 + p4);
        float4 bv = *(const float4*)(lb  + c * HW + p0 + p4);
        float4 v;
        v.x = (xv.x - mean) * rstd * wv.x + bv.x;
        v.y = (xv.y - mean) * rstd * wv.y + bv.y;
        v.z = (xv.z - mean) * rstd * wv.z + bv.z;
        v.w = (xv.w - mean) * rstd * wv.w + bv.w;
        if (which == 0) *(float4*)(gqn + c * HW + p0 + p4) = v;
        __half2 h0 = __floats2half2_rn(v.x, v.y);
        __half2 h1 = __floats2half2_rn(v.z, v.w);
        *(uint2*)(Xh + c * PX_STR + p0 * 0 + p4) = make_uint2(
            *(unsigned*)&h0, *(unsigned*)&h1);
    }
    __syncthreads();

    int wid = tid >> 5, lane = tid & 31;
    int g = lane >> 2, tig = lane & 3;
    int wn = wid * 32;
    int arow  = ((lane >> 3) & 1) * 8 + (lane & 7);
    int ahoff = (lane >> 4) * 8;

    unsigned sbp = (unsigned)__cvta_generic_to_shared(ph);

    float acc[4][4][4] = {};
#pragma unroll
    for (int kk = 0; kk < 4; kk++) {
        unsigned a[4][4], xb[2][4];
#pragma unroll
        for (int mf = 0; mf < 4; mf++)
            ldsm4(a[mf], sbp + ((mf * 16 + arow) * PW_STR + ahoff + kk * 16) * 2);
#pragma unroll
        for (int nn2 = 0; nn2 < 2; nn2++)
            ldsm4t(xb[nn2], sbp + (4608 + (kk * 16 + arow) * PX_STR
                                   + wn + nn2 * 16 + ahoff) * 2);
#pragma unroll
        for (int mf = 0; mf < 4; mf++) {
            mma_f16(acc[mf][0], a[mf], xb[0] + 0);
            mma_f16(acc[mf][1], a[mf], xb[0] + 2);
            mma_f16(acc[mf][2], a[mf], xb[1] + 0);
            mma_f16(acc[mf][3], a[mf], xb[1] + 2);
        }
    }

    if (which != 1) {
        __half* dst = (which == 0 ? g_q : g_v) + (size_t)n * CHW;
#pragma unroll
        for (int mf = 0; mf < 4; mf++) {
            int o = mf * 16 + g;
            float b0 = B[o] * wscale, b1 = B[o + 8] * wscale;
#pragma unroll
            for (int nf = 0; nf < 4; nf++) {
                int p = p0 + wn + nf * 8 + 2 * tig;
                *(__half2*)(dst + o * HW + p) =
                    __floats2half2_rn(acc[mf][nf][0] + b0, acc[mf][nf][1] + b0);
                *(__half2*)(dst + (o + 8) * HW + p) =
                    __floats2half2_rn(acc[mf][nf][2] + b1, acc[mf][nf][3] + b1);
            }
        }
    } else {
        __syncthreads();
        float* T = (float*)ph;   // [256 p][68]
#pragma unroll
        for (int mf = 0; mf < 4; mf++) {
            int o = mf * 16 + g;
            float b0 = B[o], b1 = B[o + 8];
#pragma unroll
            for (int nf = 0; nf < 4; nf++) {
                int p = wn + nf * 8 + 2 * tig;
                T[p * 68 + o]           = acc[mf][nf][0] + b0;
                T[(p + 1) * 68 + o]     = acc[mf][nf][1] + b0;
                T[p * 68 + o + 8]       = acc[mf][nf][2] + b1;
                T[(p + 1) * 68 + o + 8] = acc[mf][nf][3] + b1;
            }
        }
        __syncthreads();
        __half* dst = g_kt + (size_t)n * CHW;
        for (int idx = tid; idx < 256 * 16; idx += 256) {
            int p = idx >> 4, c4 = (idx & 15) << 2;
            __half2 h0 = __floats2half2_rn(T[p * 68 + c4],     T[p * 68 + c4 + 1]);
            __half2 h1 = __floats2half2_rn(T[p * 68 + c4 + 2], T[p * 68 + c4 + 3]);
            *(uint2*)(dst + (size_t)(p0 + p) * C + c4) = make_uint2(
                *(unsigned*)&h0, *(unsigned*)&h1);
        }
    }
}

// ---------------- 3. flash fp16 + coalesced prob output ----------------------
// grid = (8 jt, NB), block 256 (8 warps = 2 i-groups x 4 j-groups of 32x32)
// smem halves: Q[64][136] | K0,K1[64][72] | V0,V1[64][72] | P[64][136] = 71680 B
// then fp32: Pf[64][132]=33792 | sums[256] | rcol[128]  => 107008 B (2 CTA/SM)
#define H_Q   0
#define H_K0  8704
#define H_K1  (8704 + 4608)
#define H_V0  (8704 + 9216)
#define H_V1  (8704 + 13824)
#define H_P   (8704 + 18432)
#define F_PF  17920              // u32/float offset (after 35840 halves)
#define F_SUM (F_PF + 8448)
#define F_RC  (F_SUM + 256)
#define FLASH_BYTES ((F_RC + 128) * 4)   // 107008

__global__ __launch_bounds__(256, 2) void flash_kernel(
    float* __restrict__ attn_out, float* __restrict__ xout)
{
    extern __shared__ unsigned fsm[];
    __half* hsm  = (__half*)fsm;
    float*  Pf   = (float*)(fsm + F_PF);
    float*  sums = (float*)(fsm + F_SUM);
    float*  rcol = (float*)(fsm + F_RC);

    int n  = blockIdx.y;
    int j0 = blockIdx.x * JT;
    int tid = threadIdx.x;
    const __half* kt = g_kt + (size_t)n * CHW;
    const __half* qp = g_q  + (size_t)n * CHW;
    const __half* vp = g_v  + (size_t)n * CHW;

    unsigned sb = (unsigned)__cvta_generic_to_shared(fsm);

    int li[2], lc[2];
#pragma unroll
    for (int t = 0; t < 2; t++) {
        int idx = tid + t * 256;
        li[t] = idx >> 3; lc[t] = (idx & 7) * 8;
    }

#pragma unroll
    for (int t = 0; t < 4; t++) {
        int idx = tid + t * 256;
        int qr = idx >> 4, qc = (idx & 15) * 8;
        cp16(sb + (H_Q + qr * 136 + qc) * 2, qp + qr * HW + j0 + qc);
    }
#pragma unroll
    for (int t = 0; t < 2; t++)
        cp16(sb + (H_K0 + li[t] * 72 + lc[t]) * 2, kt + (size_t)li[t] * C + lc[t]);
    CP_COMMIT();

    int wid = tid >> 5, lane = tid & 31;
    int g = lane >> 2, tig = lane & 3;
    int wm = (wid & 1) * 32;
    int wj = (wid >> 1) * 32;

    int arow  = ((lane >> 3) & 1) * 8 + (lane & 7);
    int ahoff = (lane >> 4) * 8;
    unsigned kfo[2], qfo[2];
#pragma unroll
    for (int mf = 0; mf < 2; mf++)
        kfo[mf] = (unsigned)(((wm + mf * 16 + arow) * 72 + ahoff) * 2);
#pragma unroll
    for (int nn2 = 0; nn2 < 2; nn2++)
        qfo[nn2] = (unsigned)((arow * 136 + wj + nn2 * 16 + ahoff) * 2);

    unsigned qbase = sb + H_Q * 2;
    unsigned pbase = sb + H_P * 2;

    // ---------------- Phase A: column sums of exp2(logits) -------------------
    float s_run[4][2];
#pragma unroll
    for (int nf = 0; nf < 4; nf++) { s_run[nf][0] = 0.f; s_run[nf][1] = 0.f; }

    for (int ch = 0; ch < 16; ch++) {
        CP_WAIT0();
        __syncthreads();
        if (ch < 15) {
            int i0n = (ch + 1) * IC;
            unsigned koff = ((ch + 1) & 1) ? H_K1 : H_K0;
#pragma unroll
            for (int t = 0; t < 2; t++)
                cp16(sb + (koff + li[t] * 72 + lc[t]) * 2,
                     kt + (size_t)(i0n + li[t]) * C + lc[t]);
            CP_COMMIT();
        }
        unsigned kbase = sb + (((ch & 1) ? H_K1 : H_K0) * 2);

        float acc1[2][4][4] = {};
#pragma unroll
        for (int kk = 0; kk < 4; kk++) {
            unsigned a[2][4], qb[2][4];
#pragma unroll
            for (int mf = 0; mf < 2; mf++)
                ldsm4(a[mf], kbase + kfo[mf] + kk * 32);
#pragma unroll
            for (int nn2 = 0; nn2 < 2; nn2++)
                ldsm4t(qb[nn2], qbase + qfo[nn2] + kk * 4352);
#pragma unroll
            for (int mf = 0; mf < 2; mf++) {
                mma_f16(acc1[mf][0], a[mf], qb[0] + 0);
                mma_f16(acc1[mf][1], a[mf], qb[0] + 2);
                mma_f16(acc1[mf][2], a[mf], qb[1] + 0);
                mma_f16(acc1[mf][3], a[mf], qb[1] + 2);
            }
        }
#pragma unroll
        for (int mf = 0; mf < 2; mf++)
#pragma unroll
            for (int nf = 0; nf < 4; nf++) {
                s_run[nf][0] += ex2(acc1[mf][nf][0]) + ex2(acc1[mf][nf][2]);
                s_run[nf][1] += ex2(acc1[mf][nf][1]) + ex2(acc1[mf][nf][3]);
            }
    }

#pragma unroll
    for (int mask = 4; mask <= 16; mask <<= 1)
#pragma unroll
        for (int nf = 0; nf < 4; nf++)
#pragma unroll
            for (int par = 0; par < 2; par++)
                s_run[nf][par] += __shfl_xor_sync(0xFFFFFFFF, s_run[nf][par], mask);

    if (g == 0) {
#pragma unroll
        for (int nf = 0; nf < 4; nf++)
#pragma unroll
            for (int par = 0; par < 2; par++)
                sums[(wid & 1) * 128 + wj + nf * 8 + 2 * tig + par] = s_run[nf][par];
    }
    __syncthreads();
    if (tid < 128) rcol[tid] = 1.0f / (sums[tid] + sums[128 + tid]);

    // prefetch Phase B chunk 0 (K + V)
#pragma unroll
    for (int t = 0; t < 2; t++) {
        cp16(sb + (H_K0 + li[t] * 72 + lc[t]) * 2, kt + (size_t)li[t] * C + lc[t]);
        cp16(sb + (H_V0 + li[t] * 72 + lc[t]) * 2, vp + li[t] * HW + lc[t]);
    }
    CP_COMMIT();
    __syncthreads();

    float rj[4][2];
#pragma unroll
    for (int nf = 0; nf < 4; nf++)
#pragma unroll
        for (int par = 0; par < 2; par++)
            rj[nf][par] = rcol[wj + nf * 8 + 2 * tig + par];

    // ---------------- Phase B: normalized probs + V@P ------------------------
    float* ap = attn_out ? attn_out + (size_t)n * HW * HW + j0 : nullptr;
    float acc2[2][4][4] = {};

    for (int ch = 0; ch < 16; ch++) {
        CP_WAIT0();
        __syncthreads();
        if (ch < 15) {
            int i0n = (ch + 1) * IC;
            unsigned koff = ((ch + 1) & 1) ? H_K1 : H_K0;
            unsigned voff = ((ch + 1) & 1) ? H_V1 : H_V0;
#pragma unroll
            for (int t = 0; t < 2; t++) {
                cp16(sb + (koff + li[t] * 72 + lc[t]) * 2,
                     kt + (size_t)(i0n + li[t]) * C + lc[t]);
                cp16(sb + (voff + li[t] * 72 + lc[t]) * 2,
                     vp + li[t] * HW + i0n + lc[t]);
            }
            CP_COMMIT();
        }
        unsigned kbase = sb + (((ch & 1) ? H_K1 : H_K0) * 2);
        unsigned vbase = sb + (((ch & 1) ? H_V1 : H_V0) * 2);
        int i0 = ch * IC;

        float acc1[2][4][4] = {};
#pragma unroll
        for (int kk = 0; kk < 4; kk++) {
            unsigned a[2][4], qb[2][4];
#pragma unroll
            for (int mf = 0; mf < 2; mf++)
                ldsm4(a[mf], kbase + kfo[mf] + kk * 32);
#pragma unroll
            for (int nn2 = 0; nn2 < 2; nn2++)
                ldsm4t(qb[nn2], qbase + qfo[nn2] + kk * 4352);
#pragma unroll
            for (int mf = 0; mf < 2; mf++) {
                mma_f16(acc1[mf][0], a[mf], qb[0] + 0);
                mma_f16(acc1[mf][1], a[mf], qb[0] + 2);
                mma_f16(acc1[mf][2], a[mf], qb[1] + 0);
                mma_f16(acc1[mf][3], a[mf], qb[1] + 2);
            }
        }

        // normalized probs: fp32 -> Pf (smem), fp16 -> Ps (smem)
#pragma unroll
        for (int mf = 0; mf < 2; mf++) {
            int il = wm + mf * 16 + g;
#pragma unroll
            for (int nf = 0; nf < 4; nf++) {
                int col = wj + nf * 8 + 2 * tig;
                float p0 = ex2(acc1[mf][nf][0]) * rj[nf][0];
                float p1 = ex2(acc1[mf][nf][1]) * rj[nf][1];
                float p2 = ex2(acc1[mf][nf][2]) * rj[nf][0];
                float p3 = ex2(acc1[mf][nf][3]) * rj[nf][1];
                *(float2*)(Pf + il * 132 + col)       = make_float2(p0, p1);
                *(float2*)(Pf + (il + 8) * 132 + col) = make_float2(p2, p3);
                *(__half2*)(hsm + H_P + il * 136 + col)       = __floats2half2_rn(p0, p1);
                *(__half2*)(hsm + H_P + (il + 8) * 136 + col) = __floats2half2_rn(p2, p3);
            }
        }
        __syncthreads();   // Pf + Ps complete

        // coalesced prob copy-out (reads Pf; overlaps with mma2 below)
        if (ap) {
#pragma unroll
            for (int t = 0; t < 8; t++) {
                int idx = tid + t * 256;
                int r = idx >> 5, c4 = (idx & 31) << 2;
                *(float4*)(ap + (size_t)(i0 + r) * HW + c4) =
                    *(const float4*)(Pf + r * 132 + c4);
            }
        }

        if (xout) {
#pragma unroll
            for (int kk = 0; kk < 4; kk++) {
                unsigned a[2][4], pb[2][4];
#pragma unroll
                for (int mf = 0; mf < 2; mf++)
                    ldsm4(a[mf], vbase + kfo[mf] + kk * 32);
#pragma unroll
                for (int nn2 = 0; nn2 < 2; nn2++)
                    ldsm4t(pb[nn2], pbase + qfo[nn2] + kk * 4352);
#pragma unroll
                for (int mf = 0; mf < 2; mf++) {
                    mma_f16(acc2[mf][0], a[mf], pb[0] + 0);
                    mma_f16(acc2[mf][1], a[mf], pb[0] + 2);
                    mma_f16(acc2[mf][2], a[mf], pb[1] + 0);
                    mma_f16(acc2[mf][3], a[mf], pb[1] + 2);
                }
            }
        }
    }

    if (!xout) return;
    const float* qn = g_qn + (size_t)n * CHW;
    float* xp = xout + (size_t)n * CHW;
#pragma unroll
    for (int mf = 0; mf < 2; mf++) {
        int c = wm + mf * 16 + g;
#pragma unroll
        for (int nf = 0; nf < 4; nf++) {
            int j = j0 + wj + nf * 8 + 2 * tig;
            float2 q0 = *(const float2*)(qn + c * HW + j);
            float2 q1 = *(const float2*)(qn + (c + 8) * HW + j);
            *(float2*)(xp + c * HW + j) =
                make_float2(acc2[mf][nf][0] + q0.x, acc2[mf][nf][1] + q0.y);
            *(float2*)(xp + (c + 8) * HW + j) =
                make_float2(acc2[mf][nf][2] + q1.x, acc2[mf][nf][3] + q1.y);
        }
    }
}

// ---------------------------------------------------------------------------
extern "C" void kernel_launch(void* const* d_in, const int* in_sizes, int n_in,
                              void* d_out, int out_size)
{
    const float* query = (const float*)d_in[0];
    const float* key   = (const float*)d_in[1];
    const float* value = (const float*)d_in[2];
    const float* ln1w  = (const float*)d_in[3];
    const float* ln1b  = (const float*)d_in[4];
    const float* ln2w  = (const float*)d_in[5];
    const float* ln2b  = (const float*)d_in[6];
    const float* ln3w  = (const float*)d_in[7];
    const float* ln3b  = (const float*)d_in[8];
    const float* wq    = (const float*)d_in[9];
    const float* bq    = (const float*)d_in[10];
    const float* wk    = (const float*)d_in[11];
    const float* bk    = (const float*)d_in[12];
    const float* wv    = (const float*)d_in[13];
    const float* bv    = (const float*)d_in[14];

    float* out = (float*)d_out;
    const size_t XSZ = (size_t)NB * CHW;
    const size_t ASZ = (size_t)NB * HW * HW;

    float* x_out    = nullptr;
    float* attn_out = nullptr;
    size_t osz = (size_t)out_size;
    if (osz >= XSZ + ASZ)      { x_out = out; attn_out = out + XSZ; }
    else if (osz == ASZ)       { attn_out = out; }
    else                       { x_out = out; }

    static int attr_set = 0;
    if (!attr_set) {
        cudaFuncSetAttribute(proj_kernel,
                             cudaFuncAttributeMaxDynamicSharedMemorySize, PROJ_SMEM);
        cudaFuncSetAttribute(flash_kernel,
                             cudaFuncAttributeMaxDynamicSharedMemorySize, FLASH_BYTES);
        attr_set = 1;
    }

    ln_stats_kernel<<<dim3(96, 4), 256>>>(query, key, value);
    proj_kernel<<<dim3(4, NB, 3), 256, PROJ_SMEM>>>(query, key, value,
                                                    wq, bq, wk, bk, wv, bv,
                                                    ln1w, ln1b, ln2w, ln2b, ln3w, ln3b);
    flash_kernel<<<dim3(HW / JT, NB), 256, FLASH_BYTES>>>(attn_out, x_out);
}

// round 16
// speedup vs baseline: 1.9649x; 1.0348x over previous
#include <cuda_runtime.h>
#include <cuda_fp16.h>
#include <math_constants.h>

#define NB  32
#define C   64
#define HW  1024
#define CHW 65536
#define EPS 1e-5f
#define JT  128
#define IC  64
#define LSCALE 0.180336880f   // 0.125 * log2(e)

// ---------------- scratch ----------------------------------------------------
__device__ float  g_qn[NB * CHW];          // fp32 normalized query (residual)
__device__ __half g_q [NB * CHW];          // fp16, pre-scaled by LSCALE, [c][j]
__device__ __half g_kt[NB * CHW];          // fp16, K transposed [i][c]
__device__ __half g_v [NB * CHW];          // fp16, [c][i]
__device__ float  g_part[96][8][2];        // LN partial sums (8 segments)

// ---------------- helpers ----------------------------------------------------
__device__ __forceinline__ float ex2(float x) {
    float y;
    asm("ex2.approx.f32 %0, %1;" : "=f"(y) : "f"(x));
    return y;
}
__device__ __forceinline__ void mma_f16(float* d, const unsigned* a, const unsigned* b) {
    asm volatile(
        "mma.sync.aligned.m16n8k16.row.col.f32.f16.f16.f32 "
        "{%0,%1,%2,%3}, {%4,%5,%6,%7}, {%8,%9}, {%0,%1,%2,%3};\n"
        : "+f"(d[0]), "+f"(d[1]), "+f"(d[2]), "+f"(d[3])
        : "r"(a[0]), "r"(a[1]), "r"(a[2]), "r"(a[3]), "r"(b[0]), "r"(b[1]));
}
__device__ __forceinline__ void ldsm4(unsigned* r, unsigned addr) {
    asm volatile("ldmatrix.sync.aligned.m8n8.x4.shared.b16 {%0,%1,%2,%3}, [%4];"
        : "=r"(r[0]), "=r"(r[1]), "=r"(r[2]), "=r"(r[3]) : "r"(addr));
}
__device__ __forceinline__ void ldsm4t(unsigned* r, unsigned addr) {
    asm volatile("ldmatrix.sync.aligned.m8n8.x4.trans.shared.b16 {%0,%1,%2,%3}, [%4];"
        : "=r"(r[0]), "=r"(r[1]), "=r"(r[2]), "=r"(r[3]) : "r"(addr));
}
__device__ __forceinline__ void stsm4(unsigned addr, unsigned r0, unsigned r1,
                                      unsigned r2, unsigned r3) {
    asm volatile("stmatrix.sync.aligned.m8n8.x4.shared.b16 [%0], {%1,%2,%3,%4};"
        :: "r"(addr), "r"(r0), "r"(r1), "r"(r2), "r"(r3));
}
__device__ __forceinline__ void cp16(unsigned dst, const void* src) {
    asm volatile("cp.async.cg.shared.global [%0], [%1], 16;" :: "r"(dst), "l"(src));
}
#define CP_COMMIT() asm volatile("cp.async.commit_group;")
#define CP_WAIT0()  asm volatile("cp.async.wait_group 0;")

// ---------------- 1. LN stats: grid (96, 8), 256 thr ------------------------
__global__ __launch_bounds__(256) void ln_stats_kernel(
    const float* __restrict__ q, const float* __restrict__ k, const float* __restrict__ v)
{
    int t   = blockIdx.x;
    int seg = blockIdx.y;
    int which = t % 3, n = t / 3;
    const float* x = (which == 0 ? q : which == 1 ? k : v) + (size_t)n * CHW + seg * 8192;

    int tid = threadIdx.x;
    float4 a4 = make_float4(0, 0, 0, 0), q4 = make_float4(0, 0, 0, 0);
    for (int i = tid * 4; i < 8192; i += 256 * 4) {
        float4 val = *(const float4*)(x + i);
        a4.x += val.x; a4.y += val.y; a4.z += val.z; a4.w += val.w;
        q4.x += val.x * val.x; q4.y += val.y * val.y;
        q4.z += val.z * val.z; q4.w += val.w * val.w;
    }
    float s  = a4.x + a4.y + a4.z + a4.w;
    float ss = q4.x + q4.y + q4.z + q4.w;

    __shared__ float sm[256], sm2[256];
    sm[tid] = s; sm2[tid] = ss;
    __syncthreads();
    for (int o = 128; o > 0; o >>= 1) {
        if (tid < o) { sm[tid] += sm[tid + o]; sm2[tid] += sm2[tid + o]; }
        __syncthreads();
    }
    if (tid == 0) { g_part[t][seg][0] = sm[0]; g_part[t][seg][1] = sm2[0]; }
}

// ---------------- 2. projection fp16 mma; LN fused for ALL three ------------
// grid = (4 pt, NB, 3), block 256. Tile M=64(o) N=256(p) K=64(c), 4 k16 steps
#define PW_STR 72
#define PX_STR 264
#define PROJ_SMEM 69632
__global__ __launch_bounds__(256) void proj_kernel(
    const float* __restrict__ query, const float* __restrict__ key,
    const float* __restrict__ value,
    const float* __restrict__ wq, const float* __restrict__ bq,
    const float* __restrict__ wk, const float* __restrict__ bk,
    const float* __restrict__ wv, const float* __restrict__ bv,
    const float* __restrict__ ln1w, const float* __restrict__ ln1b,
    const float* __restrict__ ln2w, const float* __restrict__ ln2b,
    const float* __restrict__ ln3w, const float* __restrict__ ln3b)
{
    extern __shared__ __half ph[];
    __half* Wh = ph;
    __half* Xh = ph + 4608;

    int which = blockIdx.z;
    int n     = blockIdx.y;
    int p0    = blockIdx.x * 256;
    const float *W, *B, *raw, *lw, *lb;
    if (which == 0)      { W = wq; B = bq; raw = query; lw = ln1w; lb = ln1b; }
    else if (which == 1) { W = wk; B = bk; raw = key;   lw = ln2w; lb = ln2b; }
    else                 { W = wv; B = bv; raw = value; lw = ln3w; lb = ln3b; }
    float wscale = (which == 0) ? LSCALE : 1.0f;
    raw += (size_t)n * CHW;

    int t = n * 3 + which;
    float s = 0.f, ss = 0.f;
#pragma unroll
    for (int qq = 0; qq < 8; qq++) { s += g_part[t][qq][0]; ss += g_part[t][qq][1]; }
    float mean = s * (1.0f / CHW);
    float var  = ss * (1.0f / CHW) - mean * mean;
    float rstd = rsqrtf(var + EPS);

    int tid = threadIdx.x;
    for (int idx = tid; idx < 64 * 16; idx += 256) {
        int o = idx >> 4, c4 = (idx & 15) << 2;
        float4 v = *(const float4*)(W + o * C + c4);
        __half2 h0 = __floats2half2_rn(v.x * wscale, v.y * wscale);
        __half2 h1 = __floats2half2_rn(v.z * wscale, v.w * wscale);
        *(uint2*)(Wh + o * PW_STR + c4) = make_uint2(*(unsigned*)&h0, *(unsigned*)&h1);
    }
    float* gqn = g_qn + (size_t)n * CHW;
    for (int idx = tid; idx < 64 * 64; idx += 256) {
        int c = idx >> 6, p4 = (idx & 63) << 2;
        float4 xv = *(const float4*)(raw + c * HW + p0 + p4);
        float4 wv = *(const float4*)(lw  + c * HW + p0 + p4);
        float4 bv = *(const float4*)(lb  + c * HW + p0 + p4);
        float4 v;
        v.x = (xv.x - mean) * rstd * wv.x + bv.x;
        v.y = (xv.y - mean) * rstd * wv.y + bv.y;
        v.z = (xv.z - mean) * rstd * wv.z + bv.z;
        v.w = (xv.w - mean) * rstd * wv.w + bv.w;
        if (which == 0) *(float4*)(gqn + c * HW + p0 + p4) = v;
        __half2 h0 = __floats2half2_rn(v.x, v.y);
        __half2 h1 = __floats2half2_rn(v.z, v.w);
        *(uint2*)(Xh + c * PX_STR + p4) = make_uint2(*(unsigned*)&h0, *(unsigned*)&h1);
    }
    __syncthreads();

    int wid = tid >> 5, lane = tid & 31;
    int g = lane >> 2, tig = lane & 3;
    int wn = wid * 32;
    int arow  = ((lane >> 3) & 1) * 8 + (lane & 7);
    int ahoff = (lane >> 4) * 8;

    unsigned sbp = (unsigned)__cvta_generic_to_shared(ph);

    float acc[4][4][4] = {};
#pragma unroll
    for (int kk = 0; kk < 4; kk++) {
        unsigned a[4][4], xb[2][4];
#pragma unroll
        for (int mf = 0; mf < 4; mf++)
            ldsm4(a[mf], sbp + ((mf * 16 + arow) * PW_STR + ahoff + kk * 16) * 2);
#pragma unroll
        for (int nn2 = 0; nn2 < 2; nn2++)
            ldsm4t(xb[nn2], sbp + (4608 + (kk * 16 + arow) * PX_STR
                                   + wn + nn2 * 16 + ahoff) * 2);
#pragma unroll
        for (int mf = 0; mf < 4; mf++) {
            mma_f16(acc[mf][0], a[mf], xb[0] + 0);
            mma_f16(acc[mf][1], a[mf], xb[0] + 2);
            mma_f16(acc[mf][2], a[mf], xb[1] + 0);
            mma_f16(acc[mf][3], a[mf], xb[1] + 2);
        }
    }

    if (which != 1) {
        __half* dst = (which == 0 ? g_q : g_v) + (size_t)n * CHW;
#pragma unroll
        for (int mf = 0; mf < 4; mf++) {
            int o = mf * 16 + g;
            float b0 = B[o] * wscale, b1 = B[o + 8] * wscale;
#pragma unroll
            for (int nf = 0; nf < 4; nf++) {
                int p = p0 + wn + nf * 8 + 2 * tig;
                *(__half2*)(dst + o * HW + p) =
                    __floats2half2_rn(acc[mf][nf][0] + b0, acc[mf][nf][1] + b0);
                *(__half2*)(dst + (o + 8) * HW + p) =
                    __floats2half2_rn(acc[mf][nf][2] + b1, acc[mf][nf][3] + b1);
            }
        }
    } else {
        __syncthreads();
        float* T = (float*)ph;   // [256 p][68]
#pragma unroll
        for (int mf = 0; mf < 4; mf++) {
            int o = mf * 16 + g;
            float b0 = B[o], b1 = B[o + 8];
#pragma unroll
            for (int nf = 0; nf < 4; nf++) {
                int p = wn + nf * 8 + 2 * tig;
                T[p * 68 + o]           = acc[mf][nf][0] + b0;
                T[(p + 1) * 68 + o]     = acc[mf][nf][1] + b0;
                T[p * 68 + o + 8]       = acc[mf][nf][2] + b1;
                T[(p + 1) * 68 + o + 8] = acc[mf][nf][3] + b1;
            }
        }
        __syncthreads();
        __half* dst = g_kt + (size_t)n * CHW;
        for (int idx = tid; idx < 256 * 16; idx += 256) {
            int p = idx >> 4, c4 = (idx & 15) << 2;
            __half2 h0 = __floats2half2_rn(T[p * 68 + c4],     T[p * 68 + c4 + 1]);
            __half2 h1 = __floats2half2_rn(T[p * 68 + c4 + 2], T[p * 68 + c4 + 3]);
            *(uint2*)(dst + (size_t)(p0 + p) * C + c4) = make_uint2(
                *(unsigned*)&h0, *(unsigned*)&h1);
        }
    }
}

// ---------------- 3. flash fp16 + stmatrix Ps + coalesced prob out ----------
// grid = (8 jt, NB), block 256 (8 warps = 2 i-groups x 4 j-groups of 32x32)
#define H_Q   0
#define H_K0  8704
#define H_K1  (8704 + 4608)
#define H_V0  (8704 + 9216)
#define H_V1  (8704 + 13824)
#define H_P   (8704 + 18432)
#define F_PF  17920
#define F_SUM (F_PF + 8448)
#define F_RC  (F_SUM + 256)
#define FLASH_BYTES ((F_RC + 128) * 4)   // 107008

__global__ __launch_bounds__(256, 2) void flash_kernel(
    float* __restrict__ attn_out, float* __restrict__ xout)
{
    extern __shared__ unsigned fsm[];
    float*  Pf   = (float*)(fsm + F_PF);
    float*  sums = (float*)(fsm + F_SUM);
    float*  rcol = (float*)(fsm + F_RC);

    int n  = blockIdx.y;
    int j0 = blockIdx.x * JT;
    int tid = threadIdx.x;
    const __half* kt = g_kt + (size_t)n * CHW;
    const __half* qp = g_q  + (size_t)n * CHW;
    const __half* vp = g_v  + (size_t)n * CHW;

    unsigned sb = (unsigned)__cvta_generic_to_shared(fsm);

    int li[2], lc[2];
#pragma unroll
    for (int t = 0; t < 2; t++) {
        int idx = tid + t * 256;
        li[t] = idx >> 3; lc[t] = (idx & 7) * 8;
    }

#pragma unroll
    for (int t = 0; t < 4; t++) {
        int idx = tid + t * 256;
        int qr = idx >> 4, qc = (idx & 15) * 8;
        cp16(sb + (H_Q + qr * 136 + qc) * 2, qp + qr * HW + j0 + qc);
    }
#pragma unroll
    for (int t = 0; t < 2; t++)
        cp16(sb + (H_K0 + li[t] * 72 + lc[t]) * 2, kt + (size_t)li[t] * C + lc[t]);
    CP_COMMIT();

    int wid = tid >> 5, lane = tid & 31;
    int g = lane >> 2, tig = lane & 3;
    int wm = (wid & 1) * 32;
    int wj = (wid >> 1) * 32;

    int arow  = ((lane >> 3) & 1) * 8 + (lane & 7);
    int ahoff = (lane >> 4) * 8;
    unsigned kfo[2], qfo[2];
#pragma unroll
    for (int mf = 0; mf < 2; mf++)
        kfo[mf] = (unsigned)(((wm + mf * 16 + arow) * 72 + ahoff) * 2);
#pragma unroll
    for (int nn2 = 0; nn2 < 2; nn2++)
        qfo[nn2] = (unsigned)((arow * 136 + wj + nn2 * 16 + ahoff) * 2);
    unsigned psoff = (unsigned)((arow * 136 + ahoff) * 2);   // stmatrix lane offset

    unsigned qbase = sb + H_Q * 2;
    unsigned pbase = sb + H_P * 2;

    // ---------------- Phase A: column sums of exp2(logits) -------------------
    float s_run[4][2];
#pragma unroll
    for (int nf = 0; nf < 4; nf++) { s_run[nf][0] = 0.f; s_run[nf][1] = 0.f; }

    for (int ch = 0; ch < 16; ch++) {
        CP_WAIT0();
        __syncthreads();
        if (ch < 15) {
            int i0n = (ch + 1) * IC;
            unsigned koff = ((ch + 1) & 1) ? H_K1 : H_K0;
#pragma unroll
            for (int t = 0; t < 2; t++)
                cp16(sb + (koff + li[t] * 72 + lc[t]) * 2,
                     kt + (size_t)(i0n + li[t]) * C + lc[t]);
            CP_COMMIT();
        }
        unsigned kbase = sb + (((ch & 1) ? H_K1 : H_K0) * 2);

        float acc1[2][4][4] = {};
#pragma unroll
        for (int kk = 0; kk < 4; kk++) {
            unsigned a[2][4], qb[2][4];
#pragma unroll
            for (int mf = 0; mf < 2; mf++)
                ldsm4(a[mf], kbase + kfo[mf] + kk * 32);
#pragma unroll
            for (int nn2 = 0; nn2 < 2; nn2++)
                ldsm4t(qb[nn2], qbase + qfo[nn2] + kk * 4352);
#pragma unroll
            for (int mf = 0; mf < 2; mf++) {
                mma_f16(acc1[mf][0], a[mf], qb[0] + 0);
                mma_f16(acc1[mf][1], a[mf], qb[0] + 2);
                mma_f16(acc1[mf][2], a[mf], qb[1] + 0);
                mma_f16(acc1[mf][3], a[mf], qb[1] + 2);
            }
        }
#pragma unroll
        for (int mf = 0; mf < 2; mf++)
#pragma unroll
            for (int nf = 0; nf < 4; nf++) {
                s_run[nf][0] += ex2(acc1[mf][nf][0]) + ex2(acc1[mf][nf][2]);
                s_run[nf][1] += ex2(acc1[mf][nf][1]) + ex2(acc1[mf][nf][3]);
            }
    }

#pragma unroll
    for (int mask = 4; mask <= 16; mask <<= 1)
#pragma unroll
        for (int nf = 0; nf < 4; nf++)
#pragma unroll
            for (int par = 0; par < 2; par++)
                s_run[nf][par] += __shfl_xor_sync(0xFFFFFFFF, s_run[nf][par], mask);

    if (g == 0) {
#pragma unroll
        for (int nf = 0; nf < 4; nf++)
#pragma unroll
            for (int par = 0; par < 2; par++)
                sums[(wid & 1) * 128 + wj + nf * 8 + 2 * tig + par] = s_run[nf][par];
    }
    __syncthreads();
    if (tid < 128) rcol[tid] = 1.0f / (sums[tid] + sums[128 + tid]);

    // prefetch Phase B chunk 0 (K + V)
#pragma unroll
    for (int t = 0; t < 2; t++) {
        cp16(sb + (H_K0 + li[t] * 72 + lc[t]) * 2, kt + (size_t)li[t] * C + lc[t]);
        cp16(sb + (H_V0 + li[t] * 72 + lc[t]) * 2, vp + li[t] * HW + lc[t]);
    }
    CP_COMMIT();
    __syncthreads();

    float rj[4][2];
#pragma unroll
    for (int nf = 0; nf < 4; nf++)
#pragma unroll
        for (int par = 0; par < 2; par++)
            rj[nf][par] = rcol[wj + nf * 8 + 2 * tig + par];

    // ---------------- Phase B: normalized probs + V@P ------------------------
    float* ap = attn_out ? attn_out + (size_t)n * HW * HW + j0 : nullptr;
    float acc2[2][4][4] = {};

    for (int ch = 0; ch < 16; ch++) {
        CP_WAIT0();
        __syncthreads();
        if (ch < 15) {
            int i0n = (ch + 1) * IC;
            unsigned koff = ((ch + 1) & 1) ? H_K1 : H_K0;
            unsigned voff = ((ch + 1) & 1) ? H_V1 : H_V0;
#pragma unroll
            for (int t = 0; t < 2; t++) {
                cp16(sb + (koff + li[t] * 72 + lc[t]) * 2,
                     kt + (size_t)(i0n + li[t]) * C + lc[t]);
                cp16(sb + (voff + li[t] * 72 + lc[t]) * 2,
                     vp + li[t] * HW + i0n + lc[t]);
            }
            CP_COMMIT();
        }
        unsigned kbase = sb + (((ch & 1) ? H_K1 : H_K0) * 2);
        unsigned vbase = sb + (((ch & 1) ? H_V1 : H_V0) * 2);
        int i0 = ch * IC;

        float acc1[2][4][4] = {};
#pragma unroll
        for (int kk = 0; kk < 4; kk++) {
            unsigned a[2][4], qb[2][4];
#pragma unroll
            for (int mf = 0; mf < 2; mf++)
                ldsm4(a[mf], kbase + kfo[mf] + kk * 32);
#pragma unroll
            for (int nn2 = 0; nn2 < 2; nn2++)
                ldsm4t(qb[nn2], qbase + qfo[nn2] + kk * 4352);
#pragma unroll
            for (int mf = 0; mf < 2; mf++) {
                mma_f16(acc1[mf][0], a[mf], qb[0] + 0);
                mma_f16(acc1[mf][1], a[mf], qb[0] + 2);
                mma_f16(acc1[mf][2], a[mf], qb[1] + 0);
                mma_f16(acc1[mf][3], a[mf], qb[1] + 2);
            }
        }

        // normalized probs: fp32 -> Pf (STS), fp16 -> Ps (stmatrix x4)
#pragma unroll
        for (int mf = 0; mf < 2; mf++) {
            int il = wm + mf * 16 + g;
            __half2 hp[4][2];
#pragma unroll
            for (int nf = 0; nf < 4; nf++) {
                int col = wj + nf * 8 + 2 * tig;
                float p0 = ex2(acc1[mf][nf][0]) * rj[nf][0];
                float p1 = ex2(acc1[mf][nf][1]) * rj[nf][1];
                float p2 = ex2(acc1[mf][nf][2]) * rj[nf][0];
                float p3 = ex2(acc1[mf][nf][3]) * rj[nf][1];
                *(float2*)(Pf + il * 132 + col)       = make_float2(p0, p1);
                *(float2*)(Pf + (il + 8) * 132 + col) = make_float2(p2, p3);
                hp[nf][0] = __floats2half2_rn(p0, p1);
                hp[nf][1] = __floats2half2_rn(p2, p3);
            }
#pragma unroll
            for (int q = 0; q < 2; q++)
                stsm4(pbase + ((wm + mf * 16) * 136 + wj + q * 16) * 2 + psoff,
                      *(unsigned*)&hp[2 * q][0],     *(unsigned*)&hp[2 * q][1],
                      *(unsigned*)&hp[2 * q + 1][0], *(unsigned*)&hp[2 * q + 1][1]);
        }
        __syncthreads();   // Pf + Ps complete

        // coalesced prob copy-out
        if (ap) {
#pragma unroll
            for (int t = 0; t < 8; t++) {
                int idx = tid + t * 256;
                int r = idx >> 5, c4 = (idx & 31) << 2;
                *(float4*)(ap + (size_t)(i0 + r) * HW + c4) =
                    *(const float4*)(Pf + r * 132 + c4);
            }
        }

        if (xout) {
#pragma unroll
            for (int kk = 0; kk < 4; kk++) {
                unsigned a[2][4], pb[2][4];
#pragma unroll
                for (int mf = 0; mf < 2; mf++)
                    ldsm4(a[mf], vbase + kfo[mf] + kk * 32);
#pragma unroll
                for (int nn2 = 0; nn2 < 2; nn2++)
                    ldsm4t(pb[nn2], pbase + qfo[nn2] + kk * 4352);
#pragma unroll
                for (int mf = 0; mf < 2; mf++) {
                    mma_f16(acc2[mf][0], a[mf], pb[0] + 0);
                    mma_f16(acc2[mf][1], a[mf], pb[0] + 2);
                    mma_f16(acc2[mf][2], a[mf], pb[1] + 0);
                    mma_f16(acc2[mf][3], a[mf], pb[1] + 2);
                }
            }
        }
    }

    if (!xout) return;
    const float* qn = g_qn + (size_t)n * CHW;
    float* xp = xout + (size_t)n * CHW;
#pragma unroll
    for (int mf = 0; mf < 2; mf++) {
        int c = wm + mf * 16 + g;
#pragma unroll
        for (int nf = 0; nf < 4; nf++) {
            int j = j0 + wj + nf * 8 + 2 * tig;
            float2 q0 = *(const float2*)(qn + c * HW + j);
            float2 q1 = *(const float2*)(qn + (c + 8) * HW + j);
            *(float2*)(xp + c * HW + j) =
                make_float2(acc2[mf][nf][0] + q0.x, acc2[mf][nf][1] + q0.y);
            *(float2*)(xp + (c + 8) * HW + j) =
                make_float2(acc2[mf][nf][2] + q1.x, acc2[mf][nf][3] + q1.y);
        }
    }
}

// ---------------------------------------------------------------------------
extern "C" void kernel_launch(void* const* d_in, const int* in_sizes, int n_in,
                              void* d_out, int out_size)
{
    const float* query = (const float*)d_in[0];
    const float* key   = (const float*)d_in[1];
    const float* value = (const float*)d_in[2];
    const float* ln1w  = (const float*)d_in[3];
    const float* ln1b  = (const float*)d_in[4];
    const float* ln2w  = (const float*)d_in[5];
    const float* ln2b  = (const float*)d_in[6];
    const float* ln3w  = (const float*)d_in[7];
    const float* ln3b  = (const float*)d_in[8];
    const float* wq    = (const float*)d_in[9];
    const float* bq    = (const float*)d_in[10];
    const float* wk    = (const float*)d_in[11];
    const float* bk    = (const float*)d_in[12];
    const float* wv    = (const float*)d_in[13];
    const float* bv    = (const float*)d_in[14];

    float* out = (float*)d_out;
    const size_t XSZ = (size_t)NB * CHW;
    const size_t ASZ = (size_t)NB * HW * HW;

    float* x_out    = nullptr;
    float* attn_out = nullptr;
    size_t osz = (size_t)out_size;
    if (osz >= XSZ + ASZ)      { x_out = out; attn_out = out + XSZ; }
    else if (osz == ASZ)       { attn_out = out; }
    else                       { x_out = out; }

    static int attr_set = 0;
    if (!attr_set) {
        cudaFuncSetAttribute(proj_kernel,
                             cudaFuncAttributeMaxDynamicSharedMemorySize, PROJ_SMEM);
        cudaFuncSetAttribute(flash_kernel,
                             cudaFuncAttributeMaxDynamicSharedMemorySize, FLASH_BYTES);
        attr_set = 1;
    }

    ln_stats_kernel<<<dim3(96, 8), 256>>>(query, key, value);
    proj_kernel<<<dim3(4, NB, 3), 256, PROJ_SMEM>>>(query, key, value,
                                                    wq, bq, wk, bk, wv, bv,
                                                    ln1w, ln1b, ln2w, ln2b, ln3w, ln3b);
    flash_kernel<<<dim3(HW / JT, NB), 256, FLASH_BYTES>>>(attn_out, x_out);
}